// round 6
// baseline (speedup 1.0000x reference)
#include <cuda_runtime.h>
#include <math.h>
#include <stdint.h>

// Problem constants
#define BB 2
#define TT 2048
#define CD 768
#define HH 12
#define HDIM 64
#define DD2 32
#define FFD 3072
#define NROWS (BB*TT)          // 4096
static __device__ __constant__ float kEPS = 1e-5f;

// ---------------- scratch ----------------
__device__ float g_h [NROWS*CD];
__device__ float g_q [NROWS*CD];
__device__ float g_k [NROWS*CD];
__device__ float g_v [NROWS*CD];
__device__ float g_y [NROWS*CD];
__device__ float g_x2[NROWS*CD];
__device__ float g_ff[NROWS*FFD];
// pre-rounded (tf32-in-fp32) weight copies
__device__ float g_wqc [CD*CD];
__device__ float g_wkc [CD*CD];
__device__ float g_wvc [CD*CD];
__device__ float g_woc [CD*CD];
__device__ float g_wfcc[CD*FFD];
__device__ float g_wprc[FFD*CD];

// ---------------- helpers ----------------
__device__ __forceinline__ uint32_t f2tf32(float f) {
    uint32_t r;
    asm("cvt.rna.tf32.f32 %0, %1;" : "=r"(r) : "f"(f));
    return r;
}
__device__ __forceinline__ float rnd_tf32(float f) { return __uint_as_float(f2tf32(f)); }
__device__ __forceinline__ void mma_tf32(float* c, const uint32_t* a, const uint32_t* b) {
    asm volatile(
        "mma.sync.aligned.m16n8k8.row.col.f32.tf32.tf32.f32 "
        "{%0,%1,%2,%3}, {%4,%5,%6,%7}, {%8,%9}, {%0,%1,%2,%3};"
        : "+f"(c[0]), "+f"(c[1]), "+f"(c[2]), "+f"(c[3])
        : "r"(a[0]), "r"(a[1]), "r"(a[2]), "r"(a[3]), "r"(b[0]), "r"(b[1]));
}
__device__ __forceinline__ uint32_t smem_u32(const void* p) {
    uint32_t a;
    asm("{ .reg .u64 t; cvta.to.shared.u64 t, %1; cvt.u32.u64 %0, t; }" : "=r"(a) : "l"(p));
    return a;
}
__device__ __forceinline__ void cp16(uint32_t dst, const float* src) {
    asm volatile("cp.async.cg.shared.global [%0], [%1], 16;" :: "r"(dst), "l"(src));
}
#define CP_COMMIT() asm volatile("cp.async.commit_group;" ::: "memory")
#define CP_WAIT1()  asm volatile("cp.async.wait_group 1;" ::: "memory")

// ---------------- weight pre-round kernel ----------------
__global__ __launch_bounds__(256) void cvt_w(const float4* __restrict__ src,
                                             float4* __restrict__ dst, int n4) {
    int i = blockIdx.x * 256 + threadIdx.x;
    if (i < n4) {
        float4 v = src[i];
        v.x = rnd_tf32(v.x); v.y = rnd_tf32(v.y);
        v.z = rnd_tf32(v.z); v.w = rnd_tf32(v.w);
        dst[i] = v;
    }
}

// SMEM pipeline geometry (floats): A [128][36], B [32][136], 3 stages
#define ST_A 36
#define ST_B 136
#define A_STAGE (128 * ST_A)                 // 4608 floats
#define B_STAGE (32 * ST_B)                  // 4352 floats
#define STAGE_FLOATS (A_STAGE + B_STAGE)     // 8960 floats
#define NSTAGE 3
#define GEMM_SMEM (NSTAGE * STAGE_FLOATS * 4) // 107520 B

// ============ GEMM core: CTA 128x128, 128 thr (4 warps), warp tile 64x64 ============
struct GemmAcc { float c[4][8][4]; };   // 128 regs

__device__ __forceinline__ void gemm_mainloop(const float* __restrict__ A,
                                              const float* __restrict__ W,
                                              int M, int N, int K,
                                              int bm, int bn, float* sm,
                                              GemmAcc& G) {
    const int tid = threadIdx.x;
    const int warp = tid >> 5, lane = tid & 31;
    const int wy = warp >> 1, wx = warp & 1;
    const int gid = lane >> 2, tig = lane & 3;

    #pragma unroll
    for (int i = 0; i < 4; i++)
        #pragma unroll
        for (int j = 0; j < 8; j++)
            #pragma unroll
            for (int t = 0; t < 4; t++) G.c[i][j][t] = 0.f;

    const int NC = K >> 5;
    const uint32_t sbase = smem_u32(sm);

    // staging: per thread 8 A-granules (one full row) + 8 B-granules
    const float* Abase = A + (size_t)(bm + tid) * K;
    const uint32_t aOff = (uint32_t)(tid * (ST_A * 4));
    const int bkr = tid >> 2, bg0 = tid & 3;      // B k-row 0..31, granule base 0..3
    const float* Wbase = W + (size_t)bkr * N + bn + bg0 * 4;
    const uint32_t bOff = (uint32_t)(A_STAGE * 4 + bkr * (ST_B * 4) + bg0 * 16);

    #pragma unroll
    for (int s = 0; s < 2; s++) {
        const uint32_t st = sbase + s * (STAGE_FLOATS * 4);
        const float* Ac = Abase + s * 32;
        #pragma unroll
        for (int p = 0; p < 8; p++) cp16(st + aOff + p * 16, Ac + p * 4);
        const float* Wc = Wbase + (size_t)s * 32 * N;
        #pragma unroll
        for (int p = 0; p < 8; p++) cp16(st + bOff + p * 64, Wc + p * 16);
        CP_COMMIT();
    }

    int s = 0;
    for (int c = 0; c < NC; c++) {
        CP_WAIT1();
        __syncthreads();
        if (c + 2 < NC) {
            const int s2 = (s + 2 >= NSTAGE) ? s + 2 - NSTAGE : s + 2;
            const uint32_t st = sbase + s2 * (STAGE_FLOATS * 4);
            const float* Ac = Abase + (c + 2) * 32;
            #pragma unroll
            for (int p = 0; p < 8; p++) cp16(st + aOff + p * 16, Ac + p * 4);
            const float* Wc = Wbase + (size_t)(c + 2) * 32 * N;
            #pragma unroll
            for (int p = 0; p < 8; p++) cp16(st + bOff + p * 64, Wc + p * 16);
        }
        CP_COMMIT();

        const float* sA = sm + s * STAGE_FLOATS;
        const float* sB = sA + A_STAGE;
        #pragma unroll
        for (int ks = 0; ks < 4; ks++) {
            const int kb = ks * 8;
            uint32_t af[4][4];
            #pragma unroll
            for (int i = 0; i < 4; i++) {
                const int r0 = wy * 64 + i * 16 + gid;
                af[i][0] = __float_as_uint(sA[r0 * ST_A + kb + tig]);
                af[i][1] = __float_as_uint(sA[(r0 + 8) * ST_A + kb + tig]);
                af[i][2] = __float_as_uint(sA[r0 * ST_A + kb + tig + 4]);
                af[i][3] = __float_as_uint(sA[(r0 + 8) * ST_A + kb + tig + 4]);
            }
            uint32_t bf[8][2];
            #pragma unroll
            for (int j = 0; j < 8; j++) {
                const int cb = wx * 64 + j * 8;
                bf[j][0] = __float_as_uint(sB[(kb + tig) * ST_B + cb + gid]);
                bf[j][1] = __float_as_uint(sB[(kb + tig + 4) * ST_B + cb + gid]);
            }
            #pragma unroll
            for (int i = 0; i < 4; i++)
                #pragma unroll
                for (int j = 0; j < 8; j++) mma_tf32(G.c[i][j], af[i], bf[j]);
        }
        s = (s + 1 >= NSTAGE) ? 0 : s + 1;
    }
}

// ============ generic GEMM kernel: EPI 0 plain, 1 +R, 2 relu^2(+tf32 round) ============
template <int EPI>
__global__ __launch_bounds__(128, 2) void gemm_mma(const float* __restrict__ A,
                                                   const float* __restrict__ W,
                                                   const float* __restrict__ R,
                                                   float* __restrict__ Out,
                                                   int M, int N, int K) {
    extern __shared__ float sm[];
    const int bm = blockIdx.y * 128, bn = blockIdx.x * 128;
    GemmAcc G;
    gemm_mainloop(A, W, M, N, K, bm, bn, sm, G);

    const int tid = threadIdx.x;
    const int warp = tid >> 5, lane = tid & 31;
    const int wy = warp >> 1, wx = warp & 1;
    const int gid = lane >> 2, tig = lane & 3;

    #pragma unroll
    for (int i = 0; i < 4; i++) {
        const int r0 = bm + wy * 64 + i * 16 + gid;
        const int r1 = r0 + 8;
        #pragma unroll
        for (int j = 0; j < 8; j++) {
            const int cc = bn + wx * 64 + j * 8 + 2 * tig;
            float v0 = G.c[i][j][0], v1 = G.c[i][j][1];
            float v2 = G.c[i][j][2], v3 = G.c[i][j][3];
            if (EPI == 1) {
                float2 t0 = *(const float2*)(R + (size_t)r0 * N + cc);
                float2 t1 = *(const float2*)(R + (size_t)r1 * N + cc);
                v0 += t0.x; v1 += t0.y; v2 += t1.x; v3 += t1.y;
            }
            if (EPI == 2) {
                v0 = fmaxf(v0, 0.f); v0 = rnd_tf32(v0 * v0);
                v1 = fmaxf(v1, 0.f); v1 = rnd_tf32(v1 * v1);
                v2 = fmaxf(v2, 0.f); v2 = rnd_tf32(v2 * v2);
                v3 = fmaxf(v3, 0.f); v3 = rnd_tf32(v3 * v3);
            }
            *(float2*)(Out + (size_t)r0 * N + cc) = make_float2(v0, v1);
            *(float2*)(Out + (size_t)r1 * N + cc) = make_float2(v2, v3);
        }
    }
}

// ============ fused QKV GEMM with RoPE epilogue ============
__global__ __launch_bounds__(128, 2) void qkv_gemm(const float* __restrict__ A,
                                                   const float* __restrict__ wq,
                                                   const float* __restrict__ wk,
                                                   const float* __restrict__ wv,
                                                   const float* __restrict__ cs,
                                                   const float* __restrict__ sn,
                                                   float* __restrict__ q,
                                                   float* __restrict__ k,
                                                   float* __restrict__ v) {
    extern __shared__ float sm[];
    const int mat = blockIdx.x / 6;
    const int bn = (blockIdx.x % 6) * 128;
    const int bm = blockIdx.y * 128;
    const float* W = (mat == 0) ? wq : (mat == 1) ? wk : wv;
    float* Out = (mat == 0) ? q : (mat == 1) ? k : v;

    GemmAcc G;
    gemm_mainloop(A, W, NROWS, CD, CD, bm, bn, sm, G);

    const int tid = threadIdx.x;
    const int warp = tid >> 5, lane = tid & 31;
    const int wy = warp >> 1, wx = warp & 1;
    const int gid = lane >> 2, tig = lane & 3;

    if (mat == 2) {
        #pragma unroll
        for (int i = 0; i < 4; i++) {
            const int r0 = bm + wy * 64 + i * 16 + gid;
            const int r1 = r0 + 8;
            #pragma unroll
            for (int j = 0; j < 8; j++) {
                const int cc = bn + wx * 64 + j * 8 + 2 * tig;
                *(float2*)(Out + (size_t)r0 * CD + cc) = make_float2(G.c[i][j][0], G.c[i][j][1]);
                *(float2*)(Out + (size_t)r1 * CD + cc) = make_float2(G.c[i][j][2], G.c[i][j][3]);
            }
        }
    } else {
        // warp covers one 64-col head; pairs (d, d+32) = frags (j, j+4), j<4
        #pragma unroll
        for (int i = 0; i < 4; i++) {
            const int r0 = bm + wy * 64 + i * 16 + gid;
            const int r1 = r0 + 8;
            const int t0 = r0 & (TT - 1), t1 = r1 & (TT - 1);
            #pragma unroll
            for (int j = 0; j < 4; j++) {
                const int d = j * 8 + 2 * tig;
                const int cc = bn + wx * 64 + j * 8 + 2 * tig;
                float2 c0 = *(const float2*)(cs + t0 * DD2 + d);
                float2 s0 = *(const float2*)(sn + t0 * DD2 + d);
                float2 c1 = *(const float2*)(cs + t1 * DD2 + d);
                float2 s1 = *(const float2*)(sn + t1 * DD2 + d);
                float x1a = G.c[i][j][0], x1b = G.c[i][j][1];
                float x2a = G.c[i][j + 4][0], x2b = G.c[i][j + 4][1];
                *(float2*)(Out + (size_t)r0 * CD + cc) =
                    make_float2(x1a * c0.x + x2a * s0.x, x1b * c0.y + x2b * s0.y);
                *(float2*)(Out + (size_t)r0 * CD + cc + 32) =
                    make_float2(-x1a * s0.x + x2a * c0.x, -x1b * s0.y + x2b * c0.y);
                float y1a = G.c[i][j][2], y1b = G.c[i][j][3];
                float y2a = G.c[i][j + 4][2], y2b = G.c[i][j + 4][3];
                *(float2*)(Out + (size_t)r1 * CD + cc) =
                    make_float2(y1a * c1.x + y2a * s1.x, y1b * c1.y + y2b * s1.y);
                *(float2*)(Out + (size_t)r1 * CD + cc + 32) =
                    make_float2(-y1a * s1.x + y2a * c1.x, -y1b * s1.y + y2b * c1.y);
            }
        }
    }
}

// ---------------- RMSNorm (output pre-rounded to tf32) ----------------
__global__ __launch_bounds__(256) void rmsnorm_kernel(const float* __restrict__ x,
                                                      const float* __restrict__ g,
                                                      float* __restrict__ out) {
    int row = blockIdx.x;
    const float* xr = x + (size_t)row * CD;
    float ss = 0.f;
    for (int i = threadIdx.x; i < CD; i += 256) { float v = xr[i]; ss += v * v; }
    #pragma unroll
    for (int o = 16; o; o >>= 1) ss += __shfl_xor_sync(0xffffffffu, ss, o);
    __shared__ float red[8];
    if ((threadIdx.x & 31) == 0) red[threadIdx.x >> 5] = ss;
    __syncthreads();
    float tot = 0.f;
    #pragma unroll
    for (int i = 0; i < 8; i++) tot += red[i];
    float rinv = rsqrtf(tot / (float)CD + kEPS);
    float* orow = out + (size_t)row * CD;
    for (int i = threadIdx.x; i < CD; i += 256) orow[i] = rnd_tf32(g[i] * xr[i] * rinv);
}

// ---------------- Tensor-core Flash Attention ----------------
#define AST_K 68
#define AST_V 72
#define ATTN_SMEM ((64*AST_K + 64*AST_K + 64*AST_V) * 4)
__global__ __launch_bounds__(128, 3) void attn_mma(const float* __restrict__ q,
                                                   const float* __restrict__ k,
                                                   const float* __restrict__ v,
                                                   float* __restrict__ y) {
    extern __shared__ float asm_[];
    uint32_t* uQP = (uint32_t*)asm_;             // [64][68]
    uint32_t* uK  = uQP + 64 * AST_K;            // [64][68]
    uint32_t* uV  = uK + 64 * AST_K;             // [64][72]

    const int qt = blockIdx.x, h = blockIdx.y, b = blockIdx.z;
    const int tid = threadIdx.x, warp = tid >> 5, lane = tid & 31;
    const int gid = lane >> 2, tig = lane & 3;
    const int qs = qt * 64;
    const size_t bh = (size_t)b * TT * CD + (size_t)h * HDIM;

    for (int i = tid; i < 64 * 16; i += 128) {
        int r = i >> 4, c4 = (i & 15) * 4;
        float4 vq = *(const float4*)(q + bh + (size_t)(qs + r) * CD + c4);
        uint32_t* d = uQP + r * AST_K + c4;
        d[0] = f2tf32(vq.x * 0.125f); d[1] = f2tf32(vq.y * 0.125f);
        d[2] = f2tf32(vq.z * 0.125f); d[3] = f2tf32(vq.w * 0.125f);
    }
    __syncthreads();

    uint32_t qf[8][4];
    {
        const int r0 = warp * 16 + gid;
        #pragma unroll
        for (int kb = 0; kb < 8; kb++) {
            qf[kb][0] = uQP[r0 * AST_K + kb * 8 + tig];
            qf[kb][1] = uQP[(r0 + 8) * AST_K + kb * 8 + tig];
            qf[kb][2] = uQP[r0 * AST_K + kb * 8 + tig + 4];
            qf[kb][3] = uQP[(r0 + 8) * AST_K + kb * 8 + tig + 4];
        }
    }

    float m[2] = {-1e30f, -1e30f}, l[2] = {0.f, 0.f};
    float o[8][4];
    #pragma unroll
    for (int j = 0; j < 8; j++)
        #pragma unroll
        for (int t = 0; t < 4; t++) o[j][t] = 0.f;

    uint32_t* uP = uQP + warp * 16 * AST_K;

    for (int kt = 0; kt <= qt; kt++) {
        const int ks = kt * 64;
        __syncthreads();
        for (int i = tid; i < 64 * 16; i += 128) {
            int r = i >> 4, c4 = (i & 15) * 4;
            float4 vk = *(const float4*)(k + bh + (size_t)(ks + r) * CD + c4);
            uint32_t* dk = uK + r * AST_K + c4;
            dk[0] = f2tf32(vk.x); dk[1] = f2tf32(vk.y);
            dk[2] = f2tf32(vk.z); dk[3] = f2tf32(vk.w);
            float4 vv = *(const float4*)(v + bh + (size_t)(ks + r) * CD + c4);
            uint32_t* dv = uV + r * AST_V + c4;
            dv[0] = f2tf32(vv.x); dv[1] = f2tf32(vv.y);
            dv[2] = f2tf32(vv.z); dv[3] = f2tf32(vv.w);
        }
        __syncthreads();

        float sf[8][4];
        #pragma unroll
        for (int j = 0; j < 8; j++)
            #pragma unroll
            for (int t = 0; t < 4; t++) sf[j][t] = 0.f;
        #pragma unroll
        for (int kb = 0; kb < 8; kb++) {
            #pragma unroll
            for (int j = 0; j < 8; j++) {
                uint32_t bf[2];
                bf[0] = uK[(j * 8 + gid) * AST_K + kb * 8 + tig];
                bf[1] = uK[(j * 8 + gid) * AST_K + kb * 8 + tig + 4];
                mma_tf32(sf[j], qf[kb], bf);
            }
        }

        if (kt == qt) {
            const int qr0 = warp * 16 + gid, qr1 = qr0 + 8;
            #pragma unroll
            for (int j = 0; j < 8; j++) {
                const int kc = j * 8 + 2 * tig;
                if (kc > qr0)     sf[j][0] = -1e30f;
                if (kc + 1 > qr0) sf[j][1] = -1e30f;
                if (kc > qr1)     sf[j][2] = -1e30f;
                if (kc + 1 > qr1) sf[j][3] = -1e30f;
            }
        }

        #pragma unroll
        for (int r = 0; r < 2; r++) {
            float mx = -1e30f;
            #pragma unroll
            for (int j = 0; j < 8; j++)
                mx = fmaxf(mx, fmaxf(sf[j][2 * r], sf[j][2 * r + 1]));
            mx = fmaxf(mx, __shfl_xor_sync(0xffffffffu, mx, 1));
            mx = fmaxf(mx, __shfl_xor_sync(0xffffffffu, mx, 2));
            const float mnew = fmaxf(m[r], mx);
            const float alpha = __expf(m[r] - mnew);
            float rs = 0.f;
            #pragma unroll
            for (int j = 0; j < 8; j++) {
                float p0 = __expf(sf[j][2 * r] - mnew);
                float p1 = __expf(sf[j][2 * r + 1] - mnew);
                sf[j][2 * r] = p0; sf[j][2 * r + 1] = p1;
                rs += p0 + p1;
            }
            rs += __shfl_xor_sync(0xffffffffu, rs, 1);
            rs += __shfl_xor_sync(0xffffffffu, rs, 2);
            l[r] = l[r] * alpha + rs;
            m[r] = mnew;
            #pragma unroll
            for (int j = 0; j < 8; j++) { o[j][2 * r] *= alpha; o[j][2 * r + 1] *= alpha; }
        }

        #pragma unroll
        for (int j = 0; j < 8; j++) {
            uint32_t* d0 = uP + gid * AST_K + j * 8 + 2 * tig;
            d0[0] = f2tf32(sf[j][0]); d0[1] = f2tf32(sf[j][1]);
            uint32_t* d1 = uP + (gid + 8) * AST_K + j * 8 + 2 * tig;
            d1[0] = f2tf32(sf[j][2]); d1[1] = f2tf32(sf[j][3]);
        }
        __syncwarp();

        #pragma unroll
        for (int kb = 0; kb < 8; kb++) {
            uint32_t pa[4];
            pa[0] = uP[gid * AST_K + kb * 8 + tig];
            pa[1] = uP[(gid + 8) * AST_K + kb * 8 + tig];
            pa[2] = uP[gid * AST_K + kb * 8 + tig + 4];
            pa[3] = uP[(gid + 8) * AST_K + kb * 8 + tig + 4];
            #pragma unroll
            for (int j = 0; j < 8; j++) {
                uint32_t vb[2];
                vb[0] = uV[(kb * 8 + tig) * AST_V + j * 8 + gid];
                vb[1] = uV[(kb * 8 + tig + 4) * AST_V + j * 8 + gid];
                mma_tf32(o[j], pa, vb);
            }
        }
        __syncwarp();
    }

    // y pre-rounded to tf32 (consumed only as GEMM A operand)
    const float inv0 = 1.f / l[0], inv1 = 1.f / l[1];
    const int qa0 = qs + warp * 16 + gid, qa1 = qa0 + 8;
    #pragma unroll
    for (int j = 0; j < 8; j++) {
        const int cc = j * 8 + 2 * tig;
        *(float2*)(y + bh + (size_t)qa0 * CD + cc) =
            make_float2(rnd_tf32(o[j][0] * inv0), rnd_tf32(o[j][1] * inv0));
        *(float2*)(y + bh + (size_t)qa1 * CD + cc) =
            make_float2(rnd_tf32(o[j][2] * inv1), rnd_tf32(o[j][3] * inv1));
    }
}

// ---------------- launch ----------------
extern "C" void kernel_launch(void* const* d_in, const int* in_sizes, int n_in,
                              void* d_out, int out_size) {
    const float* x   = (const float*)d_in[0];
    const float* cs  = (const float*)d_in[1];
    const float* sn  = (const float*)d_in[2];
    const float* wq  = (const float*)d_in[3];
    const float* wk  = (const float*)d_in[4];
    const float* wv  = (const float*)d_in[5];
    const float* wo  = (const float*)d_in[6];
    const float* wfc = (const float*)d_in[7];
    const float* wpr = (const float*)d_in[8];
    const float* g1  = (const float*)d_in[9];
    const float* g2  = (const float*)d_in[10];
    float* out = (float*)d_out;

    float *h, *q, *k, *v, *y, *x2, *ff;
    float *wqc, *wkc, *wvc, *woc, *wfcc, *wprc;
    cudaGetSymbolAddress((void**)&h,  g_h);
    cudaGetSymbolAddress((void**)&q,  g_q);
    cudaGetSymbolAddress((void**)&k,  g_k);
    cudaGetSymbolAddress((void**)&v,  g_v);
    cudaGetSymbolAddress((void**)&y,  g_y);
    cudaGetSymbolAddress((void**)&x2, g_x2);
    cudaGetSymbolAddress((void**)&ff, g_ff);
    cudaGetSymbolAddress((void**)&wqc,  g_wqc);
    cudaGetSymbolAddress((void**)&wkc,  g_wkc);
    cudaGetSymbolAddress((void**)&wvc,  g_wvc);
    cudaGetSymbolAddress((void**)&woc,  g_woc);
    cudaGetSymbolAddress((void**)&wfcc, g_wfcc);
    cudaGetSymbolAddress((void**)&wprc, g_wprc);

    cudaFuncSetAttribute((const void*)attn_mma,
                         cudaFuncAttributeMaxDynamicSharedMemorySize, ATTN_SMEM);
    cudaFuncSetAttribute((const void*)qkv_gemm,
                         cudaFuncAttributeMaxDynamicSharedMemorySize, GEMM_SMEM);
    cudaFuncSetAttribute((const void*)gemm_mma<0>,
                         cudaFuncAttributeMaxDynamicSharedMemorySize, GEMM_SMEM);
    cudaFuncSetAttribute((const void*)gemm_mma<1>,
                         cudaFuncAttributeMaxDynamicSharedMemorySize, GEMM_SMEM);
    cudaFuncSetAttribute((const void*)gemm_mma<2>,
                         cudaFuncAttributeMaxDynamicSharedMemorySize, GEMM_SMEM);

    // 0. pre-round weights to tf32 (bias-free rna, once per call)
    const int nCC4 = CD * CD / 4, nCF4 = CD * FFD / 4;
    cvt_w<<<(nCC4 + 255) / 256, 256>>>((const float4*)wq,  (float4*)wqc,  nCC4);
    cvt_w<<<(nCC4 + 255) / 256, 256>>>((const float4*)wk,  (float4*)wkc,  nCC4);
    cvt_w<<<(nCC4 + 255) / 256, 256>>>((const float4*)wv,  (float4*)wvc,  nCC4);
    cvt_w<<<(nCC4 + 255) / 256, 256>>>((const float4*)wo,  (float4*)woc,  nCC4);
    cvt_w<<<(nCF4 + 255) / 256, 256>>>((const float4*)wfc, (float4*)wfcc, nCF4);
    cvt_w<<<(nCF4 + 255) / 256, 256>>>((const float4*)wpr, (float4*)wprc, nCF4);

    // 1. h = rmsnorm(x, g1)   (tf32-rounded)
    rmsnorm_kernel<<<NROWS, 256>>>(x, g1, h);

    // 2+3. q,k,v = h @ {wq,wk,wv}, RoPE fused
    qkv_gemm<<<dim3(18, 32), 128, GEMM_SMEM>>>(h, wqc, wkc, wvc, cs, sn, q, k, v);

    // 4. attention -> y (tf32-rounded)
    attn_mma<<<dim3(TT / 64, HH, BB), 128, ATTN_SMEM>>>(q, k, v, y);

    // 5. x2 = x + y @ wo
    dim3 gCC(CD / 128, NROWS / 128);
    gemm_mma<1><<<gCC, 128, GEMM_SMEM>>>(y, woc, x, x2, NROWS, CD, CD);

    // 6. h = rmsnorm(x2, g2)  (tf32-rounded)
    rmsnorm_kernel<<<NROWS, 256>>>(x2, g2, h);

    // 7. ff = relu(h @ wfc)^2 (tf32-rounded)
    dim3 gFC(FFD / 128, NROWS / 128);
    gemm_mma<2><<<gFC, 128, GEMM_SMEM>>>(h, wfcc, nullptr, ff, NROWS, FFD, CD);

    // 8. out = x2 + ff @ wpr
    gemm_mma<1><<<gCC, 128, GEMM_SMEM>>>(ff, wprc, x2, out, NROWS, CD, FFD);
}

// round 7
// speedup vs baseline: 1.3398x; 1.3398x over previous
#include <cuda_runtime.h>
#include <cuda_fp16.h>
#include <math.h>
#include <stdint.h>

// Problem constants
#define BB 2
#define TT 2048
#define CD 768
#define HH 12
#define HDIM 64
#define DD2 32
#define FFD 3072
#define NROWS (BB*TT)          // 4096
static __device__ __constant__ float kEPS = 1e-5f;

// ---------------- scratch ----------------
__device__ __half g_h [NROWS*CD];
__device__ __half g_q [NROWS*CD];
__device__ __half g_k [NROWS*CD];
__device__ __half g_v [NROWS*CD];
__device__ __half g_y [NROWS*CD];
__device__ __half g_ff[NROWS*FFD];
__device__ float  g_x2[NROWS*CD];
// transposed half weights: Wt[n][k]
__device__ __half g_wqt [CD*CD];
__device__ __half g_wkt [CD*CD];
__device__ __half g_wvt [CD*CD];
__device__ __half g_wot [CD*CD];
__device__ __half g_wfct[FFD*CD];
__device__ __half g_wprt[CD*FFD];

// ---------------- helpers ----------------
__device__ __forceinline__ void mma_f16(float* c, const uint32_t* a, const uint32_t* b) {
    asm volatile(
        "mma.sync.aligned.m16n8k16.row.col.f32.f16.f16.f32 "
        "{%0,%1,%2,%3}, {%4,%5,%6,%7}, {%8,%9}, {%0,%1,%2,%3};"
        : "+f"(c[0]), "+f"(c[1]), "+f"(c[2]), "+f"(c[3])
        : "r"(a[0]), "r"(a[1]), "r"(a[2]), "r"(a[3]), "r"(b[0]), "r"(b[1]));
}
__device__ __forceinline__ uint32_t smem_u32(const void* p) {
    uint32_t a;
    asm("{ .reg .u64 t; cvta.to.shared.u64 t, %1; cvt.u32.u64 %0, t; }" : "=r"(a) : "l"(p));
    return a;
}
__device__ __forceinline__ void cp16(uint32_t dst, const void* src) {
    asm volatile("cp.async.cg.shared.global [%0], [%1], 16;" :: "r"(dst), "l"(src));
}
#define CP_COMMIT() asm volatile("cp.async.commit_group;" ::: "memory")
#define CP_WAIT1()  asm volatile("cp.async.wait_group 1;" ::: "memory")
__device__ __forceinline__ uint32_t packh2(float a, float b) {
    __half2 h = __floats2half2_rn(a, b);
    return *(uint32_t*)&h;
}

// ---------------- weight transpose+convert: src[R][C] f32 -> dst[C][R] half ----------------
__global__ __launch_bounds__(256) void transp_h(const float* __restrict__ src,
                                                __half* __restrict__ dst, int R, int C) {
    __shared__ float t[32][33];
    const int tx = threadIdx.x & 31, ty = threadIdx.x >> 5;   // 32 x 8
    const int c0 = blockIdx.x * 32, r0 = blockIdx.y * 32;
    #pragma unroll
    for (int p = 0; p < 4; p++)
        t[ty + p * 8][tx] = src[(size_t)(r0 + ty + p * 8) * C + c0 + tx];
    __syncthreads();
    #pragma unroll
    for (int p = 0; p < 4; p++)
        dst[(size_t)(c0 + ty + p * 8) * R + r0 + tx] = __float2half_rn(t[tx][ty + p * 8]);
}

// SMEM: A [128][72]h, B [128][72]h per stage (K-chunk = 64 halfs), 3 stages
#define STH 72                          // halfs per row
#define STW 36                          // words per row
#define ROWB 144                        // bytes per row
#define A_ST_B (128 * ROWB)             // 18432 B
#define STAGE_B (2 * A_ST_B)            // 36864 B
#define NSTAGE 3
#define GEMM_SMEM (NSTAGE * STAGE_B)    // 110592 B

// ============ fp16 GEMM core: CTA 128x128, 256 thr, warp tile 32x64 ============
// A [M][K] half row-major; Wt [N][K] half (pre-transposed). K-chunk 64.
struct GemmAcc { float c[2][8][4]; };

__device__ __forceinline__ void gemm_mainloop(const __half* __restrict__ A,
                                              const __half* __restrict__ Wt,
                                              int K, int bm, int bn, char* sm,
                                              GemmAcc& G) {
    const int tid = threadIdx.x;
    const int warp = tid >> 5, lane = tid & 31;
    const int wy = warp >> 1, wx = warp & 1;
    const int gid = lane >> 2, tig = lane & 3;

    #pragma unroll
    for (int i = 0; i < 2; i++)
        #pragma unroll
        for (int j = 0; j < 8; j++)
            #pragma unroll
            for (int t = 0; t < 4; t++) G.c[i][j][t] = 0.f;

    const int NC = K >> 6;   // 64-half chunks
    const uint32_t sbase = smem_u32(sm);

    const int row = tid >> 1, gb = (tid & 1) * 4;   // 2 threads per row, 4 granules each
    const __half* Ab = A + (size_t)(bm + row) * K + gb * 8;
    const __half* Bb = Wt + (size_t)(bn + row) * K + gb * 8;
    const uint32_t aOff = (uint32_t)(row * ROWB + gb * 16);
    const uint32_t bOff = (uint32_t)(A_ST_B + row * ROWB + gb * 16);

    #pragma unroll
    for (int s = 0; s < 2; s++) {
        const uint32_t st = sbase + s * STAGE_B;
        #pragma unroll
        for (int p = 0; p < 4; p++) cp16(st + aOff + p * 16, Ab + s * 64 + p * 8);
        #pragma unroll
        for (int p = 0; p < 4; p++) cp16(st + bOff + p * 16, Bb + s * 64 + p * 8);
        CP_COMMIT();
    }

    int s = 0;
    for (int c = 0; c < NC; c++) {
        CP_WAIT1();
        __syncthreads();
        if (c + 2 < NC) {
            const int s2 = (s + 2 >= NSTAGE) ? s + 2 - NSTAGE : s + 2;
            const uint32_t st = sbase + s2 * STAGE_B;
            #pragma unroll
            for (int p = 0; p < 4; p++) cp16(st + aOff + p * 16, Ab + (c + 2) * 64 + p * 8);
            #pragma unroll
            for (int p = 0; p < 4; p++) cp16(st + bOff + p * 16, Bb + (c + 2) * 64 + p * 8);
        }
        CP_COMMIT();

        const uint32_t* uA = (const uint32_t*)(sm + s * STAGE_B);
        const uint32_t* uB = (const uint32_t*)(sm + s * STAGE_B + A_ST_B);
        #pragma unroll
        for (int ks = 0; ks < 4; ks++) {
            const int kw = ks * 8;   // word offset of this k16 step
            uint32_t af[2][4];
            #pragma unroll
            for (int i = 0; i < 2; i++) {
                const int r0 = wy * 32 + i * 16 + gid;
                af[i][0] = uA[r0 * STW + kw + tig];
                af[i][1] = uA[(r0 + 8) * STW + kw + tig];
                af[i][2] = uA[r0 * STW + kw + tig + 4];
                af[i][3] = uA[(r0 + 8) * STW + kw + tig + 4];
            }
            uint32_t bf[8][2];
            #pragma unroll
            for (int j = 0; j < 8; j++) {
                const int n = wx * 64 + j * 8 + gid;
                bf[j][0] = uB[n * STW + kw + tig];
                bf[j][1] = uB[n * STW + kw + tig + 4];
            }
            #pragma unroll
            for (int i = 0; i < 2; i++)
                #pragma unroll
                for (int j = 0; j < 8; j++) mma_f16(G.c[i][j], af[i], bf[j]);
        }
        s = (s + 1 >= NSTAGE) ? 0 : s + 1;
    }
}

// ============ GEMM kernels ============
// EPI 1: Out(f32) = acc + R(f32).  EPI 2: Out(half) = relu(acc)^2.
template <int EPI>
__global__ __launch_bounds__(256, 2) void gemm_f16(const __half* __restrict__ A,
                                                   const __half* __restrict__ Wt,
                                                   const float* __restrict__ R,
                                                   void* __restrict__ OutV,
                                                   int N, int K) {
    extern __shared__ char sm[];
    const int bm = blockIdx.y * 128, bn = blockIdx.x * 128;
    GemmAcc G;
    gemm_mainloop(A, Wt, K, bm, bn, sm, G);

    const int tid = threadIdx.x;
    const int warp = tid >> 5, lane = tid & 31;
    const int wy = warp >> 1, wx = warp & 1;
    const int gid = lane >> 2, tig = lane & 3;

    #pragma unroll
    for (int i = 0; i < 2; i++) {
        const int r0 = bm + wy * 32 + i * 16 + gid;
        const int r1 = r0 + 8;
        #pragma unroll
        for (int j = 0; j < 8; j++) {
            const int cc = bn + wx * 64 + j * 8 + 2 * tig;
            float v0 = G.c[i][j][0], v1 = G.c[i][j][1];
            float v2 = G.c[i][j][2], v3 = G.c[i][j][3];
            if (EPI == 1) {
                float* Out = (float*)OutV;
                float2 t0 = *(const float2*)(R + (size_t)r0 * N + cc);
                float2 t1 = *(const float2*)(R + (size_t)r1 * N + cc);
                *(float2*)(Out + (size_t)r0 * N + cc) = make_float2(v0 + t0.x, v1 + t0.y);
                *(float2*)(Out + (size_t)r1 * N + cc) = make_float2(v2 + t1.x, v3 + t1.y);
            } else {
                __half* Out = (__half*)OutV;
                v0 = fmaxf(v0, 0.f); v1 = fmaxf(v1, 0.f);
                v2 = fmaxf(v2, 0.f); v3 = fmaxf(v3, 0.f);
                *(uint32_t*)(Out + (size_t)r0 * N + cc) = packh2(v0 * v0, v1 * v1);
                *(uint32_t*)(Out + (size_t)r1 * N + cc) = packh2(v2 * v2, v3 * v3);
            }
        }
    }
}

// ============ fused QKV GEMM + RoPE (q pre-scaled by 1/8), half outputs ============
__global__ __launch_bounds__(256, 2) void qkv_gemm(const __half* __restrict__ A,
                                                   const __half* __restrict__ wqt,
                                                   const __half* __restrict__ wkt,
                                                   const __half* __restrict__ wvt,
                                                   const float* __restrict__ cs,
                                                   const float* __restrict__ sn,
                                                   __half* __restrict__ q,
                                                   __half* __restrict__ k,
                                                   __half* __restrict__ v) {
    extern __shared__ char sm[];
    const int mat = blockIdx.x / 6;
    const int bn = (blockIdx.x % 6) * 128;
    const int bm = blockIdx.y * 128;
    const __half* Wt = (mat == 0) ? wqt : (mat == 1) ? wkt : wvt;
    __half* Out = (mat == 0) ? q : (mat == 1) ? k : v;
    const float sc = (mat == 0) ? 0.125f : 1.0f;

    GemmAcc G;
    gemm_mainloop(A, Wt, CD, bm, bn, sm, G);

    const int tid = threadIdx.x;
    const int warp = tid >> 5, lane = tid & 31;
    const int wy = warp >> 1, wx = warp & 1;
    const int gid = lane >> 2, tig = lane & 3;

    if (mat == 2) {
        #pragma unroll
        for (int i = 0; i < 2; i++) {
            const int r0 = bm + wy * 32 + i * 16 + gid;
            const int r1 = r0 + 8;
            #pragma unroll
            for (int j = 0; j < 8; j++) {
                const int cc = bn + wx * 64 + j * 8 + 2 * tig;
                *(uint32_t*)(Out + (size_t)r0 * CD + cc) = packh2(G.c[i][j][0], G.c[i][j][1]);
                *(uint32_t*)(Out + (size_t)r1 * CD + cc) = packh2(G.c[i][j][2], G.c[i][j][3]);
            }
        }
    } else {
        #pragma unroll
        for (int i = 0; i < 2; i++) {
            const int r0 = bm + wy * 32 + i * 16 + gid;
            const int r1 = r0 + 8;
            const int t0 = r0 & (TT - 1), t1 = r1 & (TT - 1);
            #pragma unroll
            for (int j = 0; j < 4; j++) {
                const int d = j * 8 + 2 * tig;
                const int cc = bn + wx * 64 + j * 8 + 2 * tig;
                float2 c0 = *(const float2*)(cs + t0 * DD2 + d);
                float2 s0 = *(const float2*)(sn + t0 * DD2 + d);
                float2 c1 = *(const float2*)(cs + t1 * DD2 + d);
                float2 s1 = *(const float2*)(sn + t1 * DD2 + d);
                float x1a = G.c[i][j][0], x1b = G.c[i][j][1];
                float x2a = G.c[i][j + 4][0], x2b = G.c[i][j + 4][1];
                *(uint32_t*)(Out + (size_t)r0 * CD + cc) =
                    packh2(sc * (x1a * c0.x + x2a * s0.x), sc * (x1b * c0.y + x2b * s0.y));
                *(uint32_t*)(Out + (size_t)r0 * CD + cc + 32) =
                    packh2(sc * (-x1a * s0.x + x2a * c0.x), sc * (-x1b * s0.y + x2b * c0.y));
                float y1a = G.c[i][j][2], y1b = G.c[i][j][3];
                float y2a = G.c[i][j + 4][2], y2b = G.c[i][j + 4][3];
                *(uint32_t*)(Out + (size_t)r1 * CD + cc) =
                    packh2(sc * (y1a * c1.x + y2a * s1.x), sc * (y1b * c1.y + y2b * s1.y));
                *(uint32_t*)(Out + (size_t)r1 * CD + cc + 32) =
                    packh2(sc * (-y1a * s1.x + y2a * c1.x), sc * (-y1b * s1.y + y2b * c1.y));
            }
        }
    }
}

// ---------------- RMSNorm: f32 in, half out ----------------
__global__ __launch_bounds__(256) void rmsnorm_kernel(const float* __restrict__ x,
                                                      const float* __restrict__ g,
                                                      __half* __restrict__ out) {
    int row = blockIdx.x;
    const float* xr = x + (size_t)row * CD;
    float ss = 0.f;
    for (int i = threadIdx.x; i < CD; i += 256) { float v = xr[i]; ss += v * v; }
    #pragma unroll
    for (int o = 16; o; o >>= 1) ss += __shfl_xor_sync(0xffffffffu, ss, o);
    __shared__ float red[8];
    if ((threadIdx.x & 31) == 0) red[threadIdx.x >> 5] = ss;
    __syncthreads();
    float tot = 0.f;
    #pragma unroll
    for (int i = 0; i < 8; i++) tot += red[i];
    float rinv = rsqrtf(tot / (float)CD + kEPS);
    __half* orow = out + (size_t)row * CD;
    for (int i = threadIdx.x; i < CD; i += 256) orow[i] = __float2half_rn(g[i] * xr[i] * rinv);
}

// ---------------- fp16 Tensor-core Flash Attention ----------------
// smem (halfs): uQ/uP [64][72], uK [64][72], uVt [64][72]  (Vt: rows = d, cols = key)
#define AROWB 144
#define ASTW 36
#define ATTN_SMEM (3 * 64 * AROWB)      // 27648 B
__global__ __launch_bounds__(128, 4) void attn_f16(const __half* __restrict__ q,
                                                   const __half* __restrict__ k,
                                                   const __half* __restrict__ v,
                                                   __half* __restrict__ y) {
    extern __shared__ char asmc[];
    __half* uQ  = (__half*)asmc;
    __half* uK  = uQ + 64 * STH;
    __half* uVt = uK + 64 * STH;

    const int qt = blockIdx.x, h = blockIdx.y, b = blockIdx.z;
    const int tid = threadIdx.x, warp = tid >> 5, lane = tid & 31;
    const int gid = lane >> 2, tig = lane & 3;
    const int qs = qt * 64;
    const size_t bh = (size_t)b * TT * CD + (size_t)h * HDIM;

    // stage Q (q already scaled by 1/8): 64 rows x 64 halfs = 8 x 16B per row
    for (int i = tid; i < 64 * 8; i += 128) {
        const int r = i >> 3, g = i & 7;
        *(uint4*)((char*)uQ + r * AROWB + g * 16) =
            *(const uint4*)(q + bh + (size_t)(qs + r) * CD + g * 8);
    }
    __syncthreads();

    // Q fragments (register-resident): 4 k16 steps
    uint32_t qf[4][4];
    {
        const uint32_t* uQw = (const uint32_t*)uQ;
        const int r0 = warp * 16 + gid;
        #pragma unroll
        for (int kb = 0; kb < 4; kb++) {
            qf[kb][0] = uQw[r0 * ASTW + kb * 8 + tig];
            qf[kb][1] = uQw[(r0 + 8) * ASTW + kb * 8 + tig];
            qf[kb][2] = uQw[r0 * ASTW + kb * 8 + tig + 4];
            qf[kb][3] = uQw[(r0 + 8) * ASTW + kb * 8 + tig + 4];
        }
    }

    float m[2] = {-1e30f, -1e30f}, l[2] = {0.f, 0.f};
    float o[8][4];
    #pragma unroll
    for (int j = 0; j < 8; j++)
        #pragma unroll
        for (int t = 0; t < 4; t++) o[j][t] = 0.f;

    uint32_t* uPw = (uint32_t*)(uQ + warp * 16 * STH);   // warp-private P slice

    for (int kt = 0; kt <= qt; kt++) {
        const int ks = kt * 64;
        __syncthreads();
        // stage K rows
        for (int i = tid; i < 64 * 8; i += 128) {
            const int r = i >> 3, g = i & 7;
            *(uint4*)((char*)uK + r * AROWB + g * 16) =
                *(const uint4*)(k + bh + (size_t)(ks + r) * CD + g * 8);
        }
        // stage V transposed: read (r, 2dp) half2, write Vt[2dp][r], Vt[2dp+1][r]
        for (int i = tid; i < 64 * 32; i += 128) {
            const int r = i & 63, dp = i >> 6;
            __half2 vv = *(const __half2*)(v + bh + (size_t)(ks + r) * CD + 2 * dp);
            uVt[(2 * dp) * STH + r]     = __low2half(vv);
            uVt[(2 * dp + 1) * STH + r] = __high2half(vv);
        }
        __syncthreads();

        // S = Q K^T (warp tile 16x64), 4 k16 steps over d
        float sf[8][4];
        #pragma unroll
        for (int j = 0; j < 8; j++)
            #pragma unroll
            for (int t = 0; t < 4; t++) sf[j][t] = 0.f;
        {
            const uint32_t* uKw = (const uint32_t*)uK;
            #pragma unroll
            for (int kb = 0; kb < 4; kb++) {
                #pragma unroll
                for (int j = 0; j < 8; j++) {
                    uint32_t bf[2];
                    const int n = j * 8 + gid;
                    bf[0] = uKw[n * ASTW + kb * 8 + tig];
                    bf[1] = uKw[n * ASTW + kb * 8 + tig + 4];
                    mma_f16(sf[j], qf[kb], bf);
                }
            }
        }

        if (kt == qt) {
            const int qr0 = warp * 16 + gid, qr1 = qr0 + 8;
            #pragma unroll
            for (int j = 0; j < 8; j++) {
                const int kc = j * 8 + 2 * tig;
                if (kc > qr0)     sf[j][0] = -1e30f;
                if (kc + 1 > qr0) sf[j][1] = -1e30f;
                if (kc > qr1)     sf[j][2] = -1e30f;
                if (kc + 1 > qr1) sf[j][3] = -1e30f;
            }
        }

        #pragma unroll
        for (int r = 0; r < 2; r++) {
            float mx = -1e30f;
            #pragma unroll
            for (int j = 0; j < 8; j++)
                mx = fmaxf(mx, fmaxf(sf[j][2 * r], sf[j][2 * r + 1]));
            mx = fmaxf(mx, __shfl_xor_sync(0xffffffffu, mx, 1));
            mx = fmaxf(mx, __shfl_xor_sync(0xffffffffu, mx, 2));
            const float mnew = fmaxf(m[r], mx);
            const float alpha = __expf(m[r] - mnew);
            float rs = 0.f;
            #pragma unroll
            for (int j = 0; j < 8; j++) {
                float p0 = __expf(sf[j][2 * r] - mnew);
                float p1 = __expf(sf[j][2 * r + 1] - mnew);
                sf[j][2 * r] = p0; sf[j][2 * r + 1] = p1;
                rs += p0 + p1;
            }
            rs += __shfl_xor_sync(0xffffffffu, rs, 1);
            rs += __shfl_xor_sync(0xffffffffu, rs, 2);
            l[r] = l[r] * alpha + rs;
            m[r] = mnew;
            #pragma unroll
            for (int j = 0; j < 8; j++) { o[j][2 * r] *= alpha; o[j][2 * r + 1] *= alpha; }
        }

        // P -> smem as half2 (warp-private)
        #pragma unroll
        for (int j = 0; j < 8; j++) {
            uPw[gid * ASTW + j * 4 + tig]       = packh2(sf[j][0], sf[j][1]);
            uPw[(gid + 8) * ASTW + j * 4 + tig] = packh2(sf[j][2], sf[j][3]);
        }
        __syncwarp();

        // O += P V : 4 k16 steps over key
        {
            const uint32_t* uVw = (const uint32_t*)uVt;
            #pragma unroll
            for (int kb = 0; kb < 4; kb++) {
                uint32_t pa[4];
                pa[0] = uPw[gid * ASTW + kb * 8 + tig];
                pa[1] = uPw[(gid + 8) * ASTW + kb * 8 + tig];
                pa[2] = uPw[gid * ASTW + kb * 8 + tig + 4];
                pa[3] = uPw[(gid + 8) * ASTW + kb * 8 + tig + 4];
                #pragma unroll
                for (int j = 0; j < 8; j++) {
                    uint32_t vb[2];
                    const int n = j * 8 + gid;      // n = d
                    vb[0] = uVw[n * ASTW + kb * 8 + tig];
                    vb[1] = uVw[n * ASTW + kb * 8 + tig + 4];
                    mma_f16(o[j], pa, vb);
                }
            }
        }
        __syncwarp();
    }

    const float inv0 = 1.f / l[0], inv1 = 1.f / l[1];
    const int qa0 = qs + warp * 16 + gid, qa1 = qa0 + 8;
    #pragma unroll
    for (int j = 0; j < 8; j++) {
        const int cc = j * 8 + 2 * tig;
        *(uint32_t*)(y + bh + (size_t)qa0 * CD + cc) = packh2(o[j][0] * inv0, o[j][1] * inv0);
        *(uint32_t*)(y + bh + (size_t)qa1 * CD + cc) = packh2(o[j][2] * inv1, o[j][3] * inv1);
    }
}

// ---------------- launch ----------------
extern "C" void kernel_launch(void* const* d_in, const int* in_sizes, int n_in,
                              void* d_out, int out_size) {
    const float* x   = (const float*)d_in[0];
    const float* cs  = (const float*)d_in[1];
    const float* sn  = (const float*)d_in[2];
    const float* wq  = (const float*)d_in[3];
    const float* wk  = (const float*)d_in[4];
    const float* wv  = (const float*)d_in[5];
    const float* wo  = (const float*)d_in[6];
    const float* wfc = (const float*)d_in[7];
    const float* wpr = (const float*)d_in[8];
    const float* g1  = (const float*)d_in[9];
    const float* g2  = (const float*)d_in[10];
    float* out = (float*)d_out;

    __half *h, *q, *k, *v, *y, *ff;
    __half *wqt, *wkt, *wvt, *wot, *wfct, *wprt;
    float *x2;
    cudaGetSymbolAddress((void**)&h,  g_h);
    cudaGetSymbolAddress((void**)&q,  g_q);
    cudaGetSymbolAddress((void**)&k,  g_k);
    cudaGetSymbolAddress((void**)&v,  g_v);
    cudaGetSymbolAddress((void**)&y,  g_y);
    cudaGetSymbolAddress((void**)&ff, g_ff);
    cudaGetSymbolAddress((void**)&x2, g_x2);
    cudaGetSymbolAddress((void**)&wqt,  g_wqt);
    cudaGetSymbolAddress((void**)&wkt,  g_wkt);
    cudaGetSymbolAddress((void**)&wvt,  g_wvt);
    cudaGetSymbolAddress((void**)&wot,  g_wot);
    cudaGetSymbolAddress((void**)&wfct, g_wfct);
    cudaGetSymbolAddress((void**)&wprt, g_wprt);

    cudaFuncSetAttribute((const void*)attn_f16,
                         cudaFuncAttributeMaxDynamicSharedMemorySize, ATTN_SMEM);
    cudaFuncSetAttribute((const void*)qkv_gemm,
                         cudaFuncAttributeMaxDynamicSharedMemorySize, GEMM_SMEM);
    cudaFuncSetAttribute((const void*)gemm_f16<1>,
                         cudaFuncAttributeMaxDynamicSharedMemorySize, GEMM_SMEM);
    cudaFuncSetAttribute((const void*)gemm_f16<2>,
                         cudaFuncAttributeMaxDynamicSharedMemorySize, GEMM_SMEM);

    // 0. transpose+convert weights to half [n][k]
    transp_h<<<dim3(CD / 32, CD / 32), 256>>>(wq,  wqt,  CD, CD);
    transp_h<<<dim3(CD / 32, CD / 32), 256>>>(wk,  wkt,  CD, CD);
    transp_h<<<dim3(CD / 32, CD / 32), 256>>>(wv,  wvt,  CD, CD);
    transp_h<<<dim3(CD / 32, CD / 32), 256>>>(wo,  wot,  CD, CD);
    transp_h<<<dim3(FFD / 32, CD / 32), 256>>>(wfc, wfct, CD, FFD);   // [768][3072] -> [3072][768]
    transp_h<<<dim3(CD / 32, FFD / 32), 256>>>(wpr, wprt, FFD, CD);   // [3072][768] -> [768][3072]

    // 1. h = rmsnorm(x, g1)  (half)
    rmsnorm_kernel<<<NROWS, 256>>>(x, g1, h);

    // 2+3. q,k,v = h @ W, RoPE fused, q pre-scaled
    qkv_gemm<<<dim3(18, 32), 256, GEMM_SMEM>>>(h, wqt, wkt, wvt, cs, sn, q, k, v);

    // 4. attention -> y (half)
    attn_f16<<<dim3(TT / 64, HH, BB), 128, ATTN_SMEM>>>(q, k, v, y);

    // 5. x2 = x + y @ wo  (f32)
    dim3 gCC(CD / 128, NROWS / 128);
    gemm_f16<1><<<gCC, 256, GEMM_SMEM>>>(y, wot, x, x2, CD, CD);

    // 6. h = rmsnorm(x2, g2)  (half)
    rmsnorm_kernel<<<NROWS, 256>>>(x2, g2, h);

    // 7. ff = relu(h @ wfc)^2  (half)
    dim3 gFC(FFD / 128, NROWS / 128);
    gemm_f16<2><<<gFC, 256, GEMM_SMEM>>>(h, wfct, nullptr, ff, FFD, CD);

    // 8. out = x2 + ff @ wpr  (f32)
    gemm_f16<1><<<gCC, 256, GEMM_SMEM>>>(ff, wprt, x2, out, CD, FFD);
}

// round 8
// speedup vs baseline: 1.7805x; 1.3289x over previous
#include <cuda_runtime.h>
#include <cuda_fp16.h>
#include <math.h>
#include <stdint.h>

// Problem constants
#define BB 2
#define TT 2048
#define CD 768
#define HH 12
#define HDIM 64
#define DD2 32
#define FFD 3072
#define NROWS (BB*TT)          // 4096
static __device__ __constant__ float kEPS = 1e-5f;

// ---------------- scratch ----------------
__device__ __half g_h [NROWS*CD];
__device__ __half g_q [NROWS*CD];
__device__ __half g_k [NROWS*CD];
__device__ __half g_v [NROWS*CD];
__device__ __half g_y [NROWS*CD];
__device__ __half g_ff[NROWS*FFD];
__device__ float  g_x2[NROWS*CD];
__device__ __half g_wqt [CD*CD];
__device__ __half g_wkt [CD*CD];
__device__ __half g_wvt [CD*CD];
__device__ __half g_wot [CD*CD];
__device__ __half g_wfct[FFD*CD];
__device__ __half g_wprt[CD*FFD];

// ---------------- helpers ----------------
__device__ __forceinline__ void mma_f16(float* c, const uint32_t* a, const uint32_t* b) {
    asm volatile(
        "mma.sync.aligned.m16n8k16.row.col.f32.f16.f16.f32 "
        "{%0,%1,%2,%3}, {%4,%5,%6,%7}, {%8,%9}, {%0,%1,%2,%3};"
        : "+f"(c[0]), "+f"(c[1]), "+f"(c[2]), "+f"(c[3])
        : "r"(a[0]), "r"(a[1]), "r"(a[2]), "r"(a[3]), "r"(b[0]), "r"(b[1]));
}
__device__ __forceinline__ void ldsm4(uint32_t* r, uint32_t addr) {
    asm volatile("ldmatrix.sync.aligned.m8n8.x4.shared.b16 {%0,%1,%2,%3}, [%4];"
                 : "=r"(r[0]), "=r"(r[1]), "=r"(r[2]), "=r"(r[3]) : "r"(addr));
}
__device__ __forceinline__ void ldsm4t(uint32_t* r, uint32_t addr) {
    asm volatile("ldmatrix.sync.aligned.m8n8.x4.trans.shared.b16 {%0,%1,%2,%3}, [%4];"
                 : "=r"(r[0]), "=r"(r[1]), "=r"(r[2]), "=r"(r[3]) : "r"(addr));
}
__device__ __forceinline__ uint32_t smem_u32(const void* p) {
    uint32_t a;
    asm("{ .reg .u64 t; cvta.to.shared.u64 t, %1; cvt.u32.u64 %0, t; }" : "=r"(a) : "l"(p));
    return a;
}
__device__ __forceinline__ void cp16(uint32_t dst, const void* src) {
    asm volatile("cp.async.cg.shared.global [%0], [%1], 16;" :: "r"(dst), "l"(src));
}
#define CP_COMMIT() asm volatile("cp.async.commit_group;" ::: "memory")
#define CP_WAIT1()  asm volatile("cp.async.wait_group 1;" ::: "memory")
__device__ __forceinline__ uint32_t packh2(float a, float b) {
    __half2 h = __floats2half2_rn(a, b);
    return *(uint32_t*)&h;
}

// ---------------- batched weight transpose+convert ----------------
// z selects weight; tile (a,b). src[R][C] f32 -> dst[C][R] half.
__global__ __launch_bounds__(256) void transp_all(
    const float* __restrict__ wq, const float* __restrict__ wk,
    const float* __restrict__ wv, const float* __restrict__ wo,
    const float* __restrict__ wfc, const float* __restrict__ wpr,
    __half* __restrict__ wqt, __half* __restrict__ wkt,
    __half* __restrict__ wvt, __half* __restrict__ wot,
    __half* __restrict__ wfct, __half* __restrict__ wprt) {
    const int z = blockIdx.z, a = blockIdx.x, b = blockIdx.y;
    const float* src; __half* dst; int R, C, c0, r0;
    if (z < 4) {
        if (a >= 24) return;
        src = (z == 0) ? wq : (z == 1) ? wk : (z == 2) ? wv : wo;
        dst = (z == 0) ? wqt : (z == 1) ? wkt : (z == 2) ? wvt : wot;
        R = CD; C = CD; c0 = a * 32; r0 = b * 32;
    } else if (z == 4) {
        src = wfc; dst = wfct; R = CD; C = FFD; c0 = a * 32; r0 = b * 32;
    } else {
        src = wpr; dst = wprt; R = FFD; C = CD; c0 = b * 32; r0 = a * 32;
    }
    __shared__ float t[32][33];
    const int tx = threadIdx.x & 31, ty = threadIdx.x >> 5;
    #pragma unroll
    for (int p = 0; p < 4; p++)
        t[ty + p * 8][tx] = src[(size_t)(r0 + ty + p * 8) * C + c0 + tx];
    __syncthreads();
    #pragma unroll
    for (int p = 0; p < 4; p++)
        dst[(size_t)(c0 + ty + p * 8) * R + r0 + tx] = __float2half_rn(t[tx][ty + p * 8]);
}

// SMEM: A [128][72]h, B [128][72]h per stage (K-chunk 64 halfs), 3 stages
#define STH 72
#define STW 36
#define ROWB 144
#define A_ST_B (128 * ROWB)
#define STAGE_B (2 * A_ST_B)
#define NSTAGE 3
#define GEMM_SMEM (NSTAGE * STAGE_B)    // 110592 B

// ============ fp16 GEMM core with ldmatrix: CTA 128x128, 256 thr, warp 32x64 ============
struct GemmAcc { float c[2][8][4]; };

__device__ __forceinline__ void gemm_mainloop(const __half* __restrict__ A,
                                              const __half* __restrict__ Wt,
                                              int K, int bm, int bn, char* sm,
                                              GemmAcc& G) {
    const int tid = threadIdx.x;
    const int warp = tid >> 5, lane = tid & 31;
    const int wy = warp >> 1, wx = warp & 1;

    #pragma unroll
    for (int i = 0; i < 2; i++)
        #pragma unroll
        for (int j = 0; j < 8; j++)
            #pragma unroll
            for (int t = 0; t < 4; t++) G.c[i][j][t] = 0.f;

    const int NC = K >> 6;
    const uint32_t sbase = smem_u32(sm);

    // cp.async staging: 2 threads/row, 4x16B each
    const int row = tid >> 1, gb = (tid & 1) * 4;
    const __half* Ab = A + (size_t)(bm + row) * K + gb * 8;
    const __half* Bb = Wt + (size_t)(bn + row) * K + gb * 8;
    const uint32_t aOff = (uint32_t)(row * ROWB + gb * 16);
    const uint32_t bOff = (uint32_t)(A_ST_B + row * ROWB + gb * 16);

    // per-lane ldmatrix offsets
    const int l7 = lane & 7;
    const uint32_t aLd = (uint32_t)(wy * 32 + ((lane >> 3) & 1) * 8 + l7) * ROWB + (lane >> 4) * 16;
    const uint32_t bLd = (uint32_t)(wx * 64 + ((lane >> 4) & 1) * 8 + l7) * ROWB + ((lane >> 3) & 1) * 16;

    #pragma unroll
    for (int s = 0; s < 2; s++) {
        const uint32_t st = sbase + s * STAGE_B;
        #pragma unroll
        for (int p = 0; p < 4; p++) cp16(st + aOff + p * 16, Ab + s * 64 + p * 8);
        #pragma unroll
        for (int p = 0; p < 4; p++) cp16(st + bOff + p * 16, Bb + s * 64 + p * 8);
        CP_COMMIT();
    }

    int s = 0;
    for (int c = 0; c < NC; c++) {
        CP_WAIT1();
        __syncthreads();
        if (c + 2 < NC) {
            const int s2 = (s + 2 >= NSTAGE) ? s + 2 - NSTAGE : s + 2;
            const uint32_t st = sbase + s2 * STAGE_B;
            #pragma unroll
            for (int p = 0; p < 4; p++) cp16(st + aOff + p * 16, Ab + (c + 2) * 64 + p * 8);
            #pragma unroll
            for (int p = 0; p < 4; p++) cp16(st + bOff + p * 16, Bb + (c + 2) * 64 + p * 8);
        }
        CP_COMMIT();

        const uint32_t aBase = sbase + s * STAGE_B + aLd;
        const uint32_t bBase = sbase + s * STAGE_B + A_ST_B + bLd;
        #pragma unroll
        for (int ks = 0; ks < 4; ks++) {
            uint32_t af[2][4], bf[4][4];
            ldsm4(af[0], aBase + ks * 32);
            ldsm4(af[1], aBase + 16 * ROWB + ks * 32);
            #pragma unroll
            for (int p = 0; p < 4; p++) ldsm4(bf[p], bBase + p * 16 * ROWB + ks * 32);
            #pragma unroll
            for (int i = 0; i < 2; i++)
                #pragma unroll
                for (int j = 0; j < 8; j++)
                    mma_f16(G.c[i][j], af[i], &bf[j >> 1][(j & 1) * 2]);
        }
        s = (s + 1 >= NSTAGE) ? 0 : s + 1;
    }
}

// ============ GEMM kernels: EPI 1: f32 out = acc+R; EPI 2: half out = relu^2 ============
template <int EPI>
__global__ __launch_bounds__(256, 2) void gemm_f16(const __half* __restrict__ A,
                                                   const __half* __restrict__ Wt,
                                                   const float* __restrict__ R,
                                                   void* __restrict__ OutV,
                                                   int N, int K) {
    extern __shared__ char sm[];
    const int bm = blockIdx.y * 128, bn = blockIdx.x * 128;
    GemmAcc G;
    gemm_mainloop(A, Wt, K, bm, bn, sm, G);

    const int tid = threadIdx.x;
    const int warp = tid >> 5, lane = tid & 31;
    const int wy = warp >> 1, wx = warp & 1;
    const int gid = lane >> 2, tig = lane & 3;

    #pragma unroll
    for (int i = 0; i < 2; i++) {
        const int r0 = bm + wy * 32 + i * 16 + gid;
        const int r1 = r0 + 8;
        #pragma unroll
        for (int j = 0; j < 8; j++) {
            const int cc = bn + wx * 64 + j * 8 + 2 * tig;
            float v0 = G.c[i][j][0], v1 = G.c[i][j][1];
            float v2 = G.c[i][j][2], v3 = G.c[i][j][3];
            if (EPI == 1) {
                float* Out = (float*)OutV;
                float2 t0 = *(const float2*)(R + (size_t)r0 * N + cc);
                float2 t1 = *(const float2*)(R + (size_t)r1 * N + cc);
                *(float2*)(Out + (size_t)r0 * N + cc) = make_float2(v0 + t0.x, v1 + t0.y);
                *(float2*)(Out + (size_t)r1 * N + cc) = make_float2(v2 + t1.x, v3 + t1.y);
            } else {
                __half* Out = (__half*)OutV;
                v0 = fmaxf(v0, 0.f); v1 = fmaxf(v1, 0.f);
                v2 = fmaxf(v2, 0.f); v3 = fmaxf(v3, 0.f);
                *(uint32_t*)(Out + (size_t)r0 * N + cc) = packh2(v0 * v0, v1 * v1);
                *(uint32_t*)(Out + (size_t)r1 * N + cc) = packh2(v2 * v2, v3 * v3);
            }
        }
    }
}

// ============ fused QKV GEMM + RoPE (q pre-scaled by 1/8) ============
__global__ __launch_bounds__(256, 2) void qkv_gemm(const __half* __restrict__ A,
                                                   const __half* __restrict__ wqt,
                                                   const __half* __restrict__ wkt,
                                                   const __half* __restrict__ wvt,
                                                   const float* __restrict__ cs,
                                                   const float* __restrict__ sn,
                                                   __half* __restrict__ q,
                                                   __half* __restrict__ k,
                                                   __half* __restrict__ v) {
    extern __shared__ char sm[];
    const int mat = blockIdx.x / 6;
    const int bn = (blockIdx.x % 6) * 128;
    const int bm = blockIdx.y * 128;
    const __half* Wt = (mat == 0) ? wqt : (mat == 1) ? wkt : wvt;
    __half* Out = (mat == 0) ? q : (mat == 1) ? k : v;
    const float sc = (mat == 0) ? 0.125f : 1.0f;

    GemmAcc G;
    gemm_mainloop(A, Wt, CD, bm, bn, sm, G);

    const int tid = threadIdx.x;
    const int warp = tid >> 5, lane = tid & 31;
    const int wy = warp >> 1, wx = warp & 1;
    const int gid = lane >> 2, tig = lane & 3;

    if (mat == 2) {
        #pragma unroll
        for (int i = 0; i < 2; i++) {
            const int r0 = bm + wy * 32 + i * 16 + gid;
            const int r1 = r0 + 8;
            #pragma unroll
            for (int j = 0; j < 8; j++) {
                const int cc = bn + wx * 64 + j * 8 + 2 * tig;
                *(uint32_t*)(Out + (size_t)r0 * CD + cc) = packh2(G.c[i][j][0], G.c[i][j][1]);
                *(uint32_t*)(Out + (size_t)r1 * CD + cc) = packh2(G.c[i][j][2], G.c[i][j][3]);
            }
        }
    } else {
        #pragma unroll
        for (int i = 0; i < 2; i++) {
            const int r0 = bm + wy * 32 + i * 16 + gid;
            const int r1 = r0 + 8;
            const int t0 = r0 & (TT - 1), t1 = r1 & (TT - 1);
            #pragma unroll
            for (int j = 0; j < 4; j++) {
                const int d = j * 8 + 2 * tig;
                const int cc = bn + wx * 64 + j * 8 + 2 * tig;
                float2 c0 = *(const float2*)(cs + t0 * DD2 + d);
                float2 s0 = *(const float2*)(sn + t0 * DD2 + d);
                float2 c1 = *(const float2*)(cs + t1 * DD2 + d);
                float2 s1 = *(const float2*)(sn + t1 * DD2 + d);
                float x1a = G.c[i][j][0], x1b = G.c[i][j][1];
                float x2a = G.c[i][j + 4][0], x2b = G.c[i][j + 4][1];
                *(uint32_t*)(Out + (size_t)r0 * CD + cc) =
                    packh2(sc * (x1a * c0.x + x2a * s0.x), sc * (x1b * c0.y + x2b * s0.y));
                *(uint32_t*)(Out + (size_t)r0 * CD + cc + 32) =
                    packh2(sc * (-x1a * s0.x + x2a * c0.x), sc * (-x1b * s0.y + x2b * c0.y));
                float y1a = G.c[i][j][2], y1b = G.c[i][j][3];
                float y2a = G.c[i][j + 4][2], y2b = G.c[i][j + 4][3];
                *(uint32_t*)(Out + (size_t)r1 * CD + cc) =
                    packh2(sc * (y1a * c1.x + y2a * s1.x), sc * (y1b * c1.y + y2b * s1.y));
                *(uint32_t*)(Out + (size_t)r1 * CD + cc + 32) =
                    packh2(sc * (-y1a * s1.x + y2a * c1.x), sc * (-y1b * s1.y + y2b * c1.y));
            }
        }
    }
}

// ---------------- RMSNorm: f32 in, half out ----------------
__global__ __launch_bounds__(256) void rmsnorm_kernel(const float* __restrict__ x,
                                                      const float* __restrict__ g,
                                                      __half* __restrict__ out) {
    int row = blockIdx.x;
    const float* xr = x + (size_t)row * CD;
    float ss = 0.f;
    for (int i = threadIdx.x; i < CD; i += 256) { float v = xr[i]; ss += v * v; }
    #pragma unroll
    for (int o = 16; o; o >>= 1) ss += __shfl_xor_sync(0xffffffffu, ss, o);
    __shared__ float red[8];
    if ((threadIdx.x & 31) == 0) red[threadIdx.x >> 5] = ss;
    __syncthreads();
    float tot = 0.f;
    #pragma unroll
    for (int i = 0; i < 8; i++) tot += red[i];
    float rinv = rsqrtf(tot / (float)CD + kEPS);
    __half* orow = out + (size_t)row * CD;
    for (int i = threadIdx.x; i < CD; i += 256) orow[i] = __float2half_rn(g[i] * xr[i] * rinv);
}

// ---------------- fp16 Flash Attention with ldmatrix ----------------
// smem halfs: uQ/uP [64][72], uK [64][72], uV [64][72] (V row-copied; trans frags)
#define AROWB 144
#define ASTW 36
#define ATTN_SMEM (3 * 64 * AROWB)
__global__ __launch_bounds__(128, 4) void attn_f16(const __half* __restrict__ q,
                                                   const __half* __restrict__ k,
                                                   const __half* __restrict__ v,
                                                   __half* __restrict__ y) {
    extern __shared__ char asmc[];
    __half* uQ = (__half*)asmc;
    __half* uK = uQ + 64 * STH;
    __half* uV = uK + 64 * STH;

    const int qt = blockIdx.x, h = blockIdx.y, b = blockIdx.z;
    const int tid = threadIdx.x, warp = tid >> 5, lane = tid & 31;
    const int gid = lane >> 2, tig = lane & 3;
    const int qs = qt * 64;
    const size_t bh = (size_t)b * TT * CD + (size_t)h * HDIM;

    const uint32_t sQ = smem_u32(uQ), sK = smem_u32(uK), sV = smem_u32(uV);
    const int l7 = lane & 7;
    // A-style ldm offset (16-row tile): row = ((l>>3)&1)*8 + l7, colb = (l>>4)*16
    const uint32_t aLd = (uint32_t)(((lane >> 3) & 1) * 8 + l7) * AROWB + (lane >> 4) * 16;
    // B-style (K): row = ((l>>4)&1)*8 + l7 (+jj), colb = ((l>>3)&1)*16
    const uint32_t bLd = (uint32_t)(((lane >> 4) & 1) * 8 + l7) * AROWB + ((lane >> 3) & 1) * 16;
    // V trans: row = ((l>>3)&1)*8 + l7 (+kb*16), colb = ((l>>4)&1)*16 (+jj*2)
    const uint32_t vLd = (uint32_t)(((lane >> 3) & 1) * 8 + l7) * AROWB + ((lane >> 4) & 1) * 16;

    // stage Q (pre-scaled by 1/8)
    for (int i = tid; i < 64 * 8; i += 128) {
        const int r = i >> 3, g = i & 7;
        *(uint4*)((char*)uQ + r * AROWB + g * 16) =
            *(const uint4*)(q + bh + (size_t)(qs + r) * CD + g * 8);
    }
    __syncthreads();

    uint32_t qf[4][4];
    #pragma unroll
    for (int kb = 0; kb < 4; kb++)
        ldsm4(qf[kb], sQ + (uint32_t)(warp * 16) * AROWB + aLd + kb * 32);

    float m[2] = {-1e30f, -1e30f}, l[2] = {0.f, 0.f};
    float o[8][4];
    #pragma unroll
    for (int j = 0; j < 8; j++)
        #pragma unroll
        for (int t = 0; t < 4; t++) o[j][t] = 0.f;

    uint32_t* uPw = (uint32_t*)(uQ + warp * 16 * STH);
    const uint32_t sP = sQ + (uint32_t)(warp * 16) * AROWB;

    for (int kt = 0; kt <= qt; kt++) {
        const int ks = kt * 64;
        __syncthreads();
        for (int i = tid; i < 64 * 8; i += 128) {
            const int r = i >> 3, g = i & 7;
            *(uint4*)((char*)uK + r * AROWB + g * 16) =
                *(const uint4*)(k + bh + (size_t)(ks + r) * CD + g * 8);
            *(uint4*)((char*)uV + r * AROWB + g * 16) =
                *(const uint4*)(v + bh + (size_t)(ks + r) * CD + g * 8);
        }
        __syncthreads();

        // S = Q K^T
        float sf[8][4];
        #pragma unroll
        for (int j = 0; j < 8; j++)
            #pragma unroll
            for (int t = 0; t < 4; t++) sf[j][t] = 0.f;
        #pragma unroll
        for (int kb = 0; kb < 4; kb++) {
            uint32_t bf[4][4];
            #pragma unroll
            for (int p = 0; p < 4; p++)
                ldsm4(bf[p], sK + (uint32_t)(p * 16) * AROWB + bLd + kb * 32);
            #pragma unroll
            for (int j = 0; j < 8; j++)
                mma_f16(sf[j], qf[kb], &bf[j >> 1][(j & 1) * 2]);
        }

        if (kt == qt) {
            const int qr0 = warp * 16 + gid, qr1 = qr0 + 8;
            #pragma unroll
            for (int j = 0; j < 8; j++) {
                const int kc = j * 8 + 2 * tig;
                if (kc > qr0)     sf[j][0] = -1e30f;
                if (kc + 1 > qr0) sf[j][1] = -1e30f;
                if (kc > qr1)     sf[j][2] = -1e30f;
                if (kc + 1 > qr1) sf[j][3] = -1e30f;
            }
        }

        #pragma unroll
        for (int r = 0; r < 2; r++) {
            float mx = -1e30f;
            #pragma unroll
            for (int j = 0; j < 8; j++)
                mx = fmaxf(mx, fmaxf(sf[j][2 * r], sf[j][2 * r + 1]));
            mx = fmaxf(mx, __shfl_xor_sync(0xffffffffu, mx, 1));
            mx = fmaxf(mx, __shfl_xor_sync(0xffffffffu, mx, 2));
            const float mnew = fmaxf(m[r], mx);
            const float alpha = __expf(m[r] - mnew);
            float rs = 0.f;
            #pragma unroll
            for (int j = 0; j < 8; j++) {
                float p0 = __expf(sf[j][2 * r] - mnew);
                float p1 = __expf(sf[j][2 * r + 1] - mnew);
                sf[j][2 * r] = p0; sf[j][2 * r + 1] = p1;
                rs += p0 + p1;
            }
            rs += __shfl_xor_sync(0xffffffffu, rs, 1);
            rs += __shfl_xor_sync(0xffffffffu, rs, 2);
            l[r] = l[r] * alpha + rs;
            m[r] = mnew;
            #pragma unroll
            for (int j = 0; j < 8; j++) { o[j][2 * r] *= alpha; o[j][2 * r + 1] *= alpha; }
        }

        // P (half2) to warp-private slice
        #pragma unroll
        for (int j = 0; j < 8; j++) {
            uPw[gid * ASTW + j * 4 + tig]       = packh2(sf[j][0], sf[j][1]);
            uPw[(gid + 8) * ASTW + j * 4 + tig] = packh2(sf[j][2], sf[j][3]);
        }
        __syncwarp();

        // O += P V  (V fragments via ldmatrix.trans)
        #pragma unroll
        for (int kb = 0; kb < 4; kb++) {
            uint32_t pa[4];
            ldsm4(pa, sP + aLd + kb * 32);
            uint32_t vf[4][4];
            #pragma unroll
            for (int p = 0; p < 4; p++)
                ldsm4t(vf[p], sV + (uint32_t)(kb * 16) * AROWB + vLd + p * 32);
            #pragma unroll
            for (int j = 0; j < 8; j++)
                mma_f16(o[j], pa, &vf[j >> 1][(j & 1) * 2]);
        }
        __syncwarp();
    }

    const float inv0 = 1.f / l[0], inv1 = 1.f / l[1];
    const int qa0 = qs + warp * 16 + gid, qa1 = qa0 + 8;
    #pragma unroll
    for (int j = 0; j < 8; j++) {
        const int cc = j * 8 + 2 * tig;
        *(uint32_t*)(y + bh + (size_t)qa0 * CD + cc) = packh2(o[j][0] * inv0, o[j][1] * inv0);
        *(uint32_t*)(y + bh + (size_t)qa1 * CD + cc) = packh2(o[j][2] * inv1, o[j][3] * inv1);
    }
}

// ---------------- launch ----------------
extern "C" void kernel_launch(void* const* d_in, const int* in_sizes, int n_in,
                              void* d_out, int out_size) {
    const float* x   = (const float*)d_in[0];
    const float* cs  = (const float*)d_in[1];
    const float* sn  = (const float*)d_in[2];
    const float* wq  = (const float*)d_in[3];
    const float* wk  = (const float*)d_in[4];
    const float* wv  = (const float*)d_in[5];
    const float* wo  = (const float*)d_in[6];
    const float* wfc = (const float*)d_in[7];
    const float* wpr = (const float*)d_in[8];
    const float* g1  = (const float*)d_in[9];
    const float* g2  = (const float*)d_in[10];
    float* out = (float*)d_out;

    __half *h, *q, *k, *v, *y, *ff;
    __half *wqt, *wkt, *wvt, *wot, *wfct, *wprt;
    float *x2;
    cudaGetSymbolAddress((void**)&h,  g_h);
    cudaGetSymbolAddress((void**)&q,  g_q);
    cudaGetSymbolAddress((void**)&k,  g_k);
    cudaGetSymbolAddress((void**)&v,  g_v);
    cudaGetSymbolAddress((void**)&y,  g_y);
    cudaGetSymbolAddress((void**)&ff, g_ff);
    cudaGetSymbolAddress((void**)&x2, g_x2);
    cudaGetSymbolAddress((void**)&wqt,  g_wqt);
    cudaGetSymbolAddress((void**)&wkt,  g_wkt);
    cudaGetSymbolAddress((void**)&wvt,  g_wvt);
    cudaGetSymbolAddress((void**)&wot,  g_wot);
    cudaGetSymbolAddress((void**)&wfct, g_wfct);
    cudaGetSymbolAddress((void**)&wprt, g_wprt);

    cudaFuncSetAttribute((const void*)attn_f16,
                         cudaFuncAttributeMaxDynamicSharedMemorySize, ATTN_SMEM);
    cudaFuncSetAttribute((const void*)qkv_gemm,
                         cudaFuncAttributeMaxDynamicSharedMemorySize, GEMM_SMEM);
    cudaFuncSetAttribute((const void*)gemm_f16<1>,
                         cudaFuncAttributeMaxDynamicSharedMemorySize, GEMM_SMEM);
    cudaFuncSetAttribute((const void*)gemm_f16<2>,
                         cudaFuncAttributeMaxDynamicSharedMemorySize, GEMM_SMEM);

    // 0. batched transpose+convert
    transp_all<<<dim3(96, 24, 6), 256>>>(wq, wk, wv, wo, wfc, wpr,
                                         wqt, wkt, wvt, wot, wfct, wprt);

    // 1. h = rmsnorm(x, g1)
    rmsnorm_kernel<<<NROWS, 256>>>(x, g1, h);

    // 2+3. q,k,v with RoPE fused, q pre-scaled
    qkv_gemm<<<dim3(18, 32), 256, GEMM_SMEM>>>(h, wqt, wkt, wvt, cs, sn, q, k, v);

    // 4. attention -> y
    attn_f16<<<dim3(TT / 64, HH, BB), 128, ATTN_SMEM>>>(q, k, v, y);

    // 5. x2 = x + y @ wo
    dim3 gCC(CD / 128, NROWS / 128);
    gemm_f16<1><<<gCC, 256, GEMM_SMEM>>>(y, wot, x, x2, CD, CD);

    // 6. h = rmsnorm(x2, g2)
    rmsnorm_kernel<<<NROWS, 256>>>(x2, g2, h);

    // 7. ff = relu(h @ wfc)^2
    dim3 gFC(FFD / 128, NROWS / 128);
    gemm_f16<2><<<gFC, 256, GEMM_SMEM>>>(h, wfct, nullptr, ff, FFD, CD);

    // 8. out = x2 + ff @ wpr
    gemm_f16<1><<<gCC, 256, GEMM_SMEM>>>(ff, wprt, x2, out, CD, FFD);
}

// round 9
// speedup vs baseline: 1.8651x; 1.0475x over previous
#include <cuda_runtime.h>
#include <cuda_fp16.h>
#include <math.h>
#include <stdint.h>

// Problem constants
#define BB 2
#define TT 2048
#define CD 768
#define HH 12
#define HDIM 64
#define DD2 32
#define FFD 3072
#define NROWS (BB*TT)          // 4096
static __device__ __constant__ float kEPS = 1e-5f;
#define LOG2E 1.44269504088896340736f

// ---------------- scratch ----------------
__device__ __half g_h [NROWS*CD];
__device__ __half g_q [NROWS*CD];
__device__ __half g_k [NROWS*CD];
__device__ __half g_v [NROWS*CD];
__device__ __half g_y [NROWS*CD];
__device__ __half g_ff[NROWS*FFD];
__device__ float  g_x2[NROWS*CD];
__device__ __half g_wqt [CD*CD];
__device__ __half g_wkt [CD*CD];
__device__ __half g_wvt [CD*CD];
__device__ __half g_wot [CD*CD];
__device__ __half g_wfct[FFD*CD];
__device__ __half g_wprt[CD*FFD];

// ---------------- helpers ----------------
__device__ __forceinline__ void mma_f16(float* c, const uint32_t* a, const uint32_t* b) {
    asm volatile(
        "mma.sync.aligned.m16n8k16.row.col.f32.f16.f16.f32 "
        "{%0,%1,%2,%3}, {%4,%5,%6,%7}, {%8,%9}, {%0,%1,%2,%3};"
        : "+f"(c[0]), "+f"(c[1]), "+f"(c[2]), "+f"(c[3])
        : "r"(a[0]), "r"(a[1]), "r"(a[2]), "r"(a[3]), "r"(b[0]), "r"(b[1]));
}
__device__ __forceinline__ void ldsm4(uint32_t* r, uint32_t addr) {
    asm volatile("ldmatrix.sync.aligned.m8n8.x4.shared.b16 {%0,%1,%2,%3}, [%4];"
                 : "=r"(r[0]), "=r"(r[1]), "=r"(r[2]), "=r"(r[3]) : "r"(addr));
}
__device__ __forceinline__ void ldsm4t(uint32_t* r, uint32_t addr) {
    asm volatile("ldmatrix.sync.aligned.m8n8.x4.trans.shared.b16 {%0,%1,%2,%3}, [%4];"
                 : "=r"(r[0]), "=r"(r[1]), "=r"(r[2]), "=r"(r[3]) : "r"(addr));
}
__device__ __forceinline__ uint32_t smem_u32(const void* p) {
    uint32_t a;
    asm("{ .reg .u64 t; cvta.to.shared.u64 t, %1; cvt.u32.u64 %0, t; }" : "=r"(a) : "l"(p));
    return a;
}
__device__ __forceinline__ void cp16(uint32_t dst, const void* src) {
    asm volatile("cp.async.cg.shared.global [%0], [%1], 16;" :: "r"(dst), "l"(src));
}
#define CP_COMMIT() asm volatile("cp.async.commit_group;" ::: "memory")
#define CP_WAIT1()  asm volatile("cp.async.wait_group 1;" ::: "memory")
#define CP_WAIT0()  asm volatile("cp.async.wait_group 0;" ::: "memory")
__device__ __forceinline__ uint32_t packh2(float a, float b) {
    __half2 h = __floats2half2_rn(a, b);
    return *(uint32_t*)&h;
}

// ---------------- batched weight transpose+convert ----------------
__global__ __launch_bounds__(256) void transp_all(
    const float* __restrict__ wq, const float* __restrict__ wk,
    const float* __restrict__ wv, const float* __restrict__ wo,
    const float* __restrict__ wfc, const float* __restrict__ wpr,
    __half* __restrict__ wqt, __half* __restrict__ wkt,
    __half* __restrict__ wvt, __half* __restrict__ wot,
    __half* __restrict__ wfct, __half* __restrict__ wprt) {
    const int z = blockIdx.z, a = blockIdx.x, b = blockIdx.y;
    const float* src; __half* dst; int R, C, c0, r0;
    if (z < 4) {
        if (a >= 24) return;
        src = (z == 0) ? wq : (z == 1) ? wk : (z == 2) ? wv : wo;
        dst = (z == 0) ? wqt : (z == 1) ? wkt : (z == 2) ? wvt : wot;
        R = CD; C = CD; c0 = a * 32; r0 = b * 32;
    } else if (z == 4) {
        src = wfc; dst = wfct; R = CD; C = FFD; c0 = a * 32; r0 = b * 32;
    } else {
        src = wpr; dst = wprt; R = FFD; C = CD; c0 = b * 32; r0 = a * 32;
    }
    __shared__ float t[32][33];
    const int tx = threadIdx.x & 31, ty = threadIdx.x >> 5;
    #pragma unroll
    for (int p = 0; p < 4; p++)
        t[ty + p * 8][tx] = src[(size_t)(r0 + ty + p * 8) * C + c0 + tx];
    __syncthreads();
    #pragma unroll
    for (int p = 0; p < 4; p++)
        dst[(size_t)(c0 + ty + p * 8) * R + r0 + tx] = __float2half_rn(t[tx][ty + p * 8]);
}

// SMEM: A [128][72]h, B [128][72]h per stage, 3 stages
#define STH 72
#define STW 36
#define ROWB 144
#define A_ST_B (128 * ROWB)
#define STAGE_B (2 * A_ST_B)
#define NSTAGE 3
#define GEMM_SMEM (NSTAGE * STAGE_B)

// ============ fp16 GEMM core with ldmatrix ============
struct GemmAcc { float c[2][8][4]; };

__device__ __forceinline__ void gemm_mainloop(const __half* __restrict__ A,
                                              const __half* __restrict__ Wt,
                                              int K, int bm, int bn, char* sm,
                                              GemmAcc& G) {
    const int tid = threadIdx.x;
    const int warp = tid >> 5, lane = tid & 31;
    const int wy = warp >> 1, wx = warp & 1;

    #pragma unroll
    for (int i = 0; i < 2; i++)
        #pragma unroll
        for (int j = 0; j < 8; j++)
            #pragma unroll
            for (int t = 0; t < 4; t++) G.c[i][j][t] = 0.f;

    const int NC = K >> 6;
    const uint32_t sbase = smem_u32(sm);

    const int row = tid >> 1, gb = (tid & 1) * 4;
    const __half* Ab = A + (size_t)(bm + row) * K + gb * 8;
    const __half* Bb = Wt + (size_t)(bn + row) * K + gb * 8;
    const uint32_t aOff = (uint32_t)(row * ROWB + gb * 16);
    const uint32_t bOff = (uint32_t)(A_ST_B + row * ROWB + gb * 16);

    const int l7 = lane & 7;
    const uint32_t aLd = (uint32_t)(wy * 32 + ((lane >> 3) & 1) * 8 + l7) * ROWB + (lane >> 4) * 16;
    const uint32_t bLd = (uint32_t)(wx * 64 + ((lane >> 4) & 1) * 8 + l7) * ROWB + ((lane >> 3) & 1) * 16;

    #pragma unroll
    for (int s = 0; s < 2; s++) {
        const uint32_t st = sbase + s * STAGE_B;
        #pragma unroll
        for (int p = 0; p < 4; p++) cp16(st + aOff + p * 16, Ab + s * 64 + p * 8);
        #pragma unroll
        for (int p = 0; p < 4; p++) cp16(st + bOff + p * 16, Bb + s * 64 + p * 8);
        CP_COMMIT();
    }

    int s = 0;
    for (int c = 0; c < NC; c++) {
        CP_WAIT1();
        __syncthreads();
        if (c + 2 < NC) {
            const int s2 = (s + 2 >= NSTAGE) ? s + 2 - NSTAGE : s + 2;
            const uint32_t st = sbase + s2 * STAGE_B;
            #pragma unroll
            for (int p = 0; p < 4; p++) cp16(st + aOff + p * 16, Ab + (c + 2) * 64 + p * 8);
            #pragma unroll
            for (int p = 0; p < 4; p++) cp16(st + bOff + p * 16, Bb + (c + 2) * 64 + p * 8);
        }
        CP_COMMIT();

        const uint32_t aBase = sbase + s * STAGE_B + aLd;
        const uint32_t bBase = sbase + s * STAGE_B + A_ST_B + bLd;
        #pragma unroll
        for (int ks = 0; ks < 4; ks++) {
            uint32_t af[2][4], bf[4][4];
            ldsm4(af[0], aBase + ks * 32);
            ldsm4(af[1], aBase + 16 * ROWB + ks * 32);
            #pragma unroll
            for (int p = 0; p < 4; p++) ldsm4(bf[p], bBase + p * 16 * ROWB + ks * 32);
            #pragma unroll
            for (int i = 0; i < 2; i++)
                #pragma unroll
                for (int j = 0; j < 8; j++)
                    mma_f16(G.c[i][j], af[i], &bf[j >> 1][(j & 1) * 2]);
        }
        s = (s + 1 >= NSTAGE) ? 0 : s + 1;
    }
}

// ============ GEMM kernels ============
template <int EPI>
__global__ __launch_bounds__(256, 2) void gemm_f16(const __half* __restrict__ A,
                                                   const __half* __restrict__ Wt,
                                                   const float* __restrict__ R,
                                                   void* __restrict__ OutV,
                                                   int N, int K) {
    extern __shared__ char sm[];
    const int bm = blockIdx.y * 128, bn = blockIdx.x * 128;
    GemmAcc G;
    gemm_mainloop(A, Wt, K, bm, bn, sm, G);

    const int tid = threadIdx.x;
    const int warp = tid >> 5, lane = tid & 31;
    const int wy = warp >> 1, wx = warp & 1;
    const int gid = lane >> 2, tig = lane & 3;

    #pragma unroll
    for (int i = 0; i < 2; i++) {
        const int r0 = bm + wy * 32 + i * 16 + gid;
        const int r1 = r0 + 8;
        #pragma unroll
        for (int j = 0; j < 8; j++) {
            const int cc = bn + wx * 64 + j * 8 + 2 * tig;
            float v0 = G.c[i][j][0], v1 = G.c[i][j][1];
            float v2 = G.c[i][j][2], v3 = G.c[i][j][3];
            if (EPI == 1) {
                float* Out = (float*)OutV;
                float2 t0 = *(const float2*)(R + (size_t)r0 * N + cc);
                float2 t1 = *(const float2*)(R + (size_t)r1 * N + cc);
                *(float2*)(Out + (size_t)r0 * N + cc) = make_float2(v0 + t0.x, v1 + t0.y);
                *(float2*)(Out + (size_t)r1 * N + cc) = make_float2(v2 + t1.x, v3 + t1.y);
            } else {
                __half* Out = (__half*)OutV;
                v0 = fmaxf(v0, 0.f); v1 = fmaxf(v1, 0.f);
                v2 = fmaxf(v2, 0.f); v3 = fmaxf(v3, 0.f);
                *(uint32_t*)(Out + (size_t)r0 * N + cc) = packh2(v0 * v0, v1 * v1);
                *(uint32_t*)(Out + (size_t)r1 * N + cc) = packh2(v2 * v2, v3 * v3);
            }
        }
    }
}

// ============ fused QKV GEMM + RoPE (q pre-scaled by 0.125*log2e) ============
__global__ __launch_bounds__(256, 2) void qkv_gemm(const __half* __restrict__ A,
                                                   const __half* __restrict__ wqt,
                                                   const __half* __restrict__ wkt,
                                                   const __half* __restrict__ wvt,
                                                   const float* __restrict__ cs,
                                                   const float* __restrict__ sn,
                                                   __half* __restrict__ q,
                                                   __half* __restrict__ k,
                                                   __half* __restrict__ v) {
    extern __shared__ char sm[];
    const int mat = blockIdx.x / 6;
    const int bn = (blockIdx.x % 6) * 128;
    const int bm = blockIdx.y * 128;
    const __half* Wt = (mat == 0) ? wqt : (mat == 1) ? wkt : wvt;
    __half* Out = (mat == 0) ? q : (mat == 1) ? k : v;
    const float sc = (mat == 0) ? 0.125f * LOG2E : 1.0f;

    GemmAcc G;
    gemm_mainloop(A, Wt, CD, bm, bn, sm, G);

    const int tid = threadIdx.x;
    const int warp = tid >> 5, lane = tid & 31;
    const int wy = warp >> 1, wx = warp & 1;
    const int gid = lane >> 2, tig = lane & 3;

    if (mat == 2) {
        #pragma unroll
        for (int i = 0; i < 2; i++) {
            const int r0 = bm + wy * 32 + i * 16 + gid;
            const int r1 = r0 + 8;
            #pragma unroll
            for (int j = 0; j < 8; j++) {
                const int cc = bn + wx * 64 + j * 8 + 2 * tig;
                *(uint32_t*)(Out + (size_t)r0 * CD + cc) = packh2(G.c[i][j][0], G.c[i][j][1]);
                *(uint32_t*)(Out + (size_t)r1 * CD + cc) = packh2(G.c[i][j][2], G.c[i][j][3]);
            }
        }
    } else {
        #pragma unroll
        for (int i = 0; i < 2; i++) {
            const int r0 = bm + wy * 32 + i * 16 + gid;
            const int r1 = r0 + 8;
            const int t0 = r0 & (TT - 1), t1 = r1 & (TT - 1);
            #pragma unroll
            for (int j = 0; j < 4; j++) {
                const int d = j * 8 + 2 * tig;
                const int cc = bn + wx * 64 + j * 8 + 2 * tig;
                float2 c0 = *(const float2*)(cs + t0 * DD2 + d);
                float2 s0 = *(const float2*)(sn + t0 * DD2 + d);
                float2 c1 = *(const float2*)(cs + t1 * DD2 + d);
                float2 s1 = *(const float2*)(sn + t1 * DD2 + d);
                float x1a = G.c[i][j][0], x1b = G.c[i][j][1];
                float x2a = G.c[i][j + 4][0], x2b = G.c[i][j + 4][1];
                *(uint32_t*)(Out + (size_t)r0 * CD + cc) =
                    packh2(sc * (x1a * c0.x + x2a * s0.x), sc * (x1b * c0.y + x2b * s0.y));
                *(uint32_t*)(Out + (size_t)r0 * CD + cc + 32) =
                    packh2(sc * (-x1a * s0.x + x2a * c0.x), sc * (-x1b * s0.y + x2b * c0.y));
                float y1a = G.c[i][j][2], y1b = G.c[i][j][3];
                float y2a = G.c[i][j + 4][2], y2b = G.c[i][j + 4][3];
                *(uint32_t*)(Out + (size_t)r1 * CD + cc) =
                    packh2(sc * (y1a * c1.x + y2a * s1.x), sc * (y1b * c1.y + y2b * s1.y));
                *(uint32_t*)(Out + (size_t)r1 * CD + cc + 32) =
                    packh2(sc * (-y1a * s1.x + y2a * c1.x), sc * (-y1b * s1.y + y2b * c1.y));
            }
        }
    }
}

// ---------------- RMSNorm: f32 in, half out ----------------
__global__ __launch_bounds__(256) void rmsnorm_kernel(const float* __restrict__ x,
                                                      const float* __restrict__ g,
                                                      __half* __restrict__ out) {
    int row = blockIdx.x;
    const float* xr = x + (size_t)row * CD;
    float ss = 0.f;
    for (int i = threadIdx.x; i < CD; i += 256) { float v = xr[i]; ss += v * v; }
    #pragma unroll
    for (int o = 16; o; o >>= 1) ss += __shfl_xor_sync(0xffffffffu, ss, o);
    __shared__ float red[8];
    if ((threadIdx.x & 31) == 0) red[threadIdx.x >> 5] = ss;
    __syncthreads();
    float tot = 0.f;
    #pragma unroll
    for (int i = 0; i < 8; i++) tot += red[i];
    float rinv = rsqrtf(tot / (float)CD + kEPS);
    __half* orow = out + (size_t)row * CD;
    for (int i = threadIdx.x; i < CD; i += 256) orow[i] = __float2half_rn(g[i] * xr[i] * rinv);
}

// ---------------- fp16 Flash Attention: 128 q-rows, 8 warps, cp.async K/V ----------------
// smem halfs: uQ [128][72] (also per-warp P slices), then 2 x { K [64][72], V [64][72] }
#define KV_H (64 * STH)                 // halfs per K or V tile
#define ATTN_SMEM ((128 * STH + 4 * KV_H) * 2)   // 55296 B
__global__ __launch_bounds__(256, 2) void attn_f16(const __half* __restrict__ q,
                                                   const __half* __restrict__ k,
                                                   const __half* __restrict__ v,
                                                   __half* __restrict__ y) {
    extern __shared__ char asmc[];
    __half* uQ = (__half*)asmc;

    const int h = blockIdx.y, b = blockIdx.z;
    const int qtb = (int)gridDim.x - 1 - (int)blockIdx.x;   // big tiles first
    const int tid = threadIdx.x, warp = tid >> 5, lane = tid & 31;
    const int gid = lane >> 2, tig = lane & 3;
    const int qs = qtb * 128;
    const size_t bh = (size_t)b * TT * CD + (size_t)h * HDIM;

    const uint32_t sQ = smem_u32(uQ);
    const uint32_t kvBase[2] = { sQ + 128 * ROWB, sQ + 128 * ROWB + 2 * KV_H * 2 };
    const int l7 = lane & 7;
    const uint32_t aLd = (uint32_t)(((lane >> 3) & 1) * 8 + l7) * ROWB + (lane >> 4) * 16;
    const uint32_t bLd = (uint32_t)(((lane >> 4) & 1) * 8 + l7) * ROWB + ((lane >> 3) & 1) * 16;
    const uint32_t vLd = (uint32_t)(((lane >> 3) & 1) * 8 + l7) * ROWB + ((lane >> 4) & 1) * 16;

    // stage Q (pre-scaled): 128 rows x 8 granules, 4 per thread
    for (int i = tid; i < 128 * 8; i += 256) {
        const int r = i >> 3, g = i & 7;
        *(uint4*)((char*)uQ + r * ROWB + g * 16) =
            *(const uint4*)(q + bh + (size_t)(qs + r) * CD + g * 8);
    }
    __syncthreads();

    uint32_t qf[4][4];
    #pragma unroll
    for (int kb = 0; kb < 4; kb++)
        ldsm4(qf[kb], sQ + (uint32_t)(warp * 16) * ROWB + aLd + kb * 32);

    float m[2] = {-1e30f, -1e30f}, l[2] = {0.f, 0.f};
    float o[8][4];
    #pragma unroll
    for (int j = 0; j < 8; j++)
        #pragma unroll
        for (int t = 0; t < 4; t++) o[j][t] = 0.f;

    uint32_t* uPw = (uint32_t*)(uQ + warp * 16 * STH);
    const uint32_t sP = sQ + (uint32_t)(warp * 16) * ROWB;
    const int qrow0 = qs + warp * 16;   // warp's lowest q row

    const int nk = 2 * qtb + 2;

    // prologue: stage tile 0 (K+V): 512 granules each, 2 per thread
    {
        const int r = tid >> 3, g = tid & 7;          // 2 rows apart: tid and tid+256
        #pragma unroll
        for (int p = 0; p < 2; p++) {
            const int rr = r + p * 32;
            cp16(kvBase[0] + rr * ROWB + g * 16, k + bh + (size_t)rr * CD + g * 8);
            cp16(kvBase[0] + KV_H * 2 + rr * ROWB + g * 16, v + bh + (size_t)rr * CD + g * 8);
        }
        CP_COMMIT();
    }

    for (int kt = 0; kt < nk; kt++) {
        CP_WAIT0();
        __syncthreads();
        if (kt + 1 < nk) {
            const uint32_t dstb = kvBase[(kt + 1) & 1];
            const int ks1 = (kt + 1) * 64;
            const int r = tid >> 3, g = tid & 7;
            #pragma unroll
            for (int p = 0; p < 2; p++) {
                const int rr = r + p * 32;
                cp16(dstb + rr * ROWB + g * 16, k + bh + (size_t)(ks1 + rr) * CD + g * 8);
                cp16(dstb + KV_H * 2 + rr * ROWB + g * 16, v + bh + (size_t)(ks1 + rr) * CD + g * 8);
            }
        }
        CP_COMMIT();

        const int ks = kt * 64;
        const uint32_t sK = kvBase[kt & 1];
        const uint32_t sV = sK + KV_H * 2;

        // S = Q K^T
        float sf[8][4];
        #pragma unroll
        for (int j = 0; j < 8; j++)
            #pragma unroll
            for (int t = 0; t < 4; t++) sf[j][t] = 0.f;
        #pragma unroll
        for (int kb = 0; kb < 4; kb++) {
            uint32_t bf[4][4];
            #pragma unroll
            for (int p = 0; p < 4; p++)
                ldsm4(bf[p], sK + (uint32_t)(p * 16) * ROWB + bLd + kb * 32);
            #pragma unroll
            for (int j = 0; j < 8; j++)
                mma_f16(sf[j], qf[kb], &bf[j >> 1][(j & 1) * 2]);
        }

        // causal mask (global indices) when this tile can cross the diagonal
        if (ks + 63 > qrow0) {
            const int qr0 = qrow0 + gid, qr1 = qr0 + 8;
            #pragma unroll
            for (int j = 0; j < 8; j++) {
                const int kc = ks + j * 8 + 2 * tig;
                if (kc > qr0)     sf[j][0] = -1e30f;
                if (kc + 1 > qr0) sf[j][1] = -1e30f;
                if (kc > qr1)     sf[j][2] = -1e30f;
                if (kc + 1 > qr1) sf[j][3] = -1e30f;
            }
        }

        #pragma unroll
        for (int r = 0; r < 2; r++) {
            float mx = -1e30f;
            #pragma unroll
            for (int j = 0; j < 8; j++)
                mx = fmaxf(mx, fmaxf(sf[j][2 * r], sf[j][2 * r + 1]));
            mx = fmaxf(mx, __shfl_xor_sync(0xffffffffu, mx, 1));
            mx = fmaxf(mx, __shfl_xor_sync(0xffffffffu, mx, 2));
            const float mnew = fmaxf(m[r], mx);
            const float alpha = exp2f(m[r] - mnew);
            float rs = 0.f;
            #pragma unroll
            for (int j = 0; j < 8; j++) {
                float p0 = exp2f(sf[j][2 * r] - mnew);
                float p1 = exp2f(sf[j][2 * r + 1] - mnew);
                sf[j][2 * r] = p0; sf[j][2 * r + 1] = p1;
                rs += p0 + p1;
            }
            rs += __shfl_xor_sync(0xffffffffu, rs, 1);
            rs += __shfl_xor_sync(0xffffffffu, rs, 2);
            l[r] = l[r] * alpha + rs;
            m[r] = mnew;
            #pragma unroll
            for (int j = 0; j < 8; j++) { o[j][2 * r] *= alpha; o[j][2 * r + 1] *= alpha; }
        }

        // P (half2) to warp-private slice
        #pragma unroll
        for (int j = 0; j < 8; j++) {
            uPw[gid * STW + j * 4 + tig]       = packh2(sf[j][0], sf[j][1]);
            uPw[(gid + 8) * STW + j * 4 + tig] = packh2(sf[j][2], sf[j][3]);
        }
        __syncwarp();

        // O += P V (trans fragments)
        #pragma unroll
        for (int kb = 0; kb < 4; kb++) {
            uint32_t pa[4];
            ldsm4(pa, sP + aLd + kb * 32);
            uint32_t vf[4][4];
            #pragma unroll
            for (int p = 0; p < 4; p++)
                ldsm4t(vf[p], sV + (uint32_t)(kb * 16) * ROWB + vLd + p * 32);
            #pragma unroll
            for (int j = 0; j < 8; j++)
                mma_f16(o[j], pa, &vf[j >> 1][(j & 1) * 2]);
        }
        __syncwarp();
    }

    const float inv0 = 1.f / l[0], inv1 = 1.f / l[1];
    const int qa0 = qs + warp * 16 + gid, qa1 = qa0 + 8;
    #pragma unroll
    for (int j = 0; j < 8; j++) {
        const int cc = j * 8 + 2 * tig;
        *(uint32_t*)(y + bh + (size_t)qa0 * CD + cc) = packh2(o[j][0] * inv0, o[j][1] * inv0);
        *(uint32_t*)(y + bh + (size_t)qa1 * CD + cc) = packh2(o[j][2] * inv1, o[j][3] * inv1);
    }
}

// ---------------- launch ----------------
extern "C" void kernel_launch(void* const* d_in, const int* in_sizes, int n_in,
                              void* d_out, int out_size) {
    const float* x   = (const float*)d_in[0];
    const float* cs  = (const float*)d_in[1];
    const float* sn  = (const float*)d_in[2];
    const float* wq  = (const float*)d_in[3];
    const float* wk  = (const float*)d_in[4];
    const float* wv  = (const float*)d_in[5];
    const float* wo  = (const float*)d_in[6];
    const float* wfc = (const float*)d_in[7];
    const float* wpr = (const float*)d_in[8];
    const float* g1  = (const float*)d_in[9];
    const float* g2  = (const float*)d_in[10];
    float* out = (float*)d_out;

    __half *h, *q, *k, *v, *y, *ff;
    __half *wqt, *wkt, *wvt, *wot, *wfct, *wprt;
    float *x2;
    cudaGetSymbolAddress((void**)&h,  g_h);
    cudaGetSymbolAddress((void**)&q,  g_q);
    cudaGetSymbolAddress((void**)&k,  g_k);
    cudaGetSymbolAddress((void**)&v,  g_v);
    cudaGetSymbolAddress((void**)&y,  g_y);
    cudaGetSymbolAddress((void**)&ff, g_ff);
    cudaGetSymbolAddress((void**)&x2, g_x2);
    cudaGetSymbolAddress((void**)&wqt,  g_wqt);
    cudaGetSymbolAddress((void**)&wkt,  g_wkt);
    cudaGetSymbolAddress((void**)&wvt,  g_wvt);
    cudaGetSymbolAddress((void**)&wot,  g_wot);
    cudaGetSymbolAddress((void**)&wfct, g_wfct);
    cudaGetSymbolAddress((void**)&wprt, g_wprt);

    cudaFuncSetAttribute((const void*)attn_f16,
                         cudaFuncAttributeMaxDynamicSharedMemorySize, ATTN_SMEM);
    cudaFuncSetAttribute((const void*)qkv_gemm,
                         cudaFuncAttributeMaxDynamicSharedMemorySize, GEMM_SMEM);
    cudaFuncSetAttribute((const void*)gemm_f16<1>,
                         cudaFuncAttributeMaxDynamicSharedMemorySize, GEMM_SMEM);
    cudaFuncSetAttribute((const void*)gemm_f16<2>,
                         cudaFuncAttributeMaxDynamicSharedMemorySize, GEMM_SMEM);

    // 0. batched transpose+convert
    transp_all<<<dim3(96, 24, 6), 256>>>(wq, wk, wv, wo, wfc, wpr,
                                         wqt, wkt, wvt, wot, wfct, wprt);

    // 1. h = rmsnorm(x, g1)
    rmsnorm_kernel<<<NROWS, 256>>>(x, g1, h);

    // 2+3. q,k,v with RoPE fused, q pre-scaled by 0.125*log2e
    qkv_gemm<<<dim3(18, 32), 256, GEMM_SMEM>>>(h, wqt, wkt, wvt, cs, sn, q, k, v);

    // 4. attention -> y
    attn_f16<<<dim3(TT / 128, HH, BB), 256, ATTN_SMEM>>>(q, k, v, y);

    // 5. x2 = x + y @ wo
    dim3 gCC(CD / 128, NROWS / 128);
    gemm_f16<1><<<gCC, 256, GEMM_SMEM>>>(y, wot, x, x2, CD, CD);

    // 6. h = rmsnorm(x2, g2)
    rmsnorm_kernel<<<NROWS, 256>>>(x2, g2, h);

    // 7. ff = relu(h @ wfc)^2
    dim3 gFC(FFD / 128, NROWS / 128);
    gemm_f16<2><<<gFC, 256, GEMM_SMEM>>>(h, wfct, nullptr, ff, FFD, CD);

    // 8. out = x2 + ff @ wpr
    gemm_f16<1><<<gCC, 256, GEMM_SMEM>>>(ff, wprt, x2, out, CD, FFD);
}

// round 10
// speedup vs baseline: 1.8989x; 1.0181x over previous
#include <cuda_runtime.h>
#include <cuda_fp16.h>
#include <math.h>
#include <stdint.h>

// Problem constants
#define BB 2
#define TT 2048
#define CD 768
#define HH 12
#define HDIM 64
#define DD2 32
#define FFD 3072
#define NROWS (BB*TT)          // 4096
static __device__ __constant__ float kEPS = 1e-5f;
#define LOG2E 1.44269504088896340736f

// ---------------- scratch ----------------
__device__ __half g_h [NROWS*CD];
__device__ __half g_q [NROWS*CD];
__device__ __half g_k [NROWS*CD];
__device__ __half g_v [NROWS*CD];
__device__ __half g_y [NROWS*CD];
__device__ __half g_ff[NROWS*FFD];
__device__ float  g_x2[NROWS*CD];
__device__ __half g_wqt [CD*CD];
__device__ __half g_wkt [CD*CD];
__device__ __half g_wvt [CD*CD];
__device__ __half g_wot [CD*CD];
__device__ __half g_wfct[FFD*CD];
__device__ __half g_wprt[CD*FFD];

// ---------------- helpers ----------------
__device__ __forceinline__ void mma_f16(float* c, const uint32_t* a, const uint32_t* b) {
    asm volatile(
        "mma.sync.aligned.m16n8k16.row.col.f32.f16.f16.f32 "
        "{%0,%1,%2,%3}, {%4,%5,%6,%7}, {%8,%9}, {%0,%1,%2,%3};"
        : "+f"(c[0]), "+f"(c[1]), "+f"(c[2]), "+f"(c[3])
        : "r"(a[0]), "r"(a[1]), "r"(a[2]), "r"(a[3]), "r"(b[0]), "r"(b[1]));
}
__device__ __forceinline__ void ldsm4(uint32_t* r, uint32_t addr) {
    asm volatile("ldmatrix.sync.aligned.m8n8.x4.shared.b16 {%0,%1,%2,%3}, [%4];"
                 : "=r"(r[0]), "=r"(r[1]), "=r"(r[2]), "=r"(r[3]) : "r"(addr));
}
__device__ __forceinline__ void ldsm4t(uint32_t* r, uint32_t addr) {
    asm volatile("ldmatrix.sync.aligned.m8n8.x4.trans.shared.b16 {%0,%1,%2,%3}, [%4];"
                 : "=r"(r[0]), "=r"(r[1]), "=r"(r[2]), "=r"(r[3]) : "r"(addr));
}
__device__ __forceinline__ uint32_t smem_u32(const void* p) {
    uint32_t a;
    asm("{ .reg .u64 t; cvta.to.shared.u64 t, %1; cvt.u32.u64 %0, t; }" : "=r"(a) : "l"(p));
    return a;
}
__device__ __forceinline__ void cp16(uint32_t dst, const void* src) {
    asm volatile("cp.async.cg.shared.global [%0], [%1], 16;" :: "r"(dst), "l"(src));
}
#define CP_COMMIT() asm volatile("cp.async.commit_group;" ::: "memory")
#define CP_WAIT1()  asm volatile("cp.async.wait_group 1;" ::: "memory")
#define CP_WAIT0()  asm volatile("cp.async.wait_group 0;" ::: "memory")
__device__ __forceinline__ uint32_t packh2(float a, float b) {
    __half2 h = __floats2half2_rn(a, b);
    return *(uint32_t*)&h;
}

// ---------------- batched weight transpose+convert ----------------
__global__ __launch_bounds__(256) void transp_all(
    const float* __restrict__ wq, const float* __restrict__ wk,
    const float* __restrict__ wv, const float* __restrict__ wo,
    const float* __restrict__ wfc, const float* __restrict__ wpr,
    __half* __restrict__ wqt, __half* __restrict__ wkt,
    __half* __restrict__ wvt, __half* __restrict__ wot,
    __half* __restrict__ wfct, __half* __restrict__ wprt) {
    const int z = blockIdx.z, a = blockIdx.x, b = blockIdx.y;
    const float* src; __half* dst; int R, C, c0, r0;
    if (z < 4) {
        if (a >= 24) return;
        src = (z == 0) ? wq : (z == 1) ? wk : (z == 2) ? wv : wo;
        dst = (z == 0) ? wqt : (z == 1) ? wkt : (z == 2) ? wvt : wot;
        R = CD; C = CD; c0 = a * 32; r0 = b * 32;
    } else if (z == 4) {
        src = wfc; dst = wfct; R = CD; C = FFD; c0 = a * 32; r0 = b * 32;
    } else {
        src = wpr; dst = wprt; R = FFD; C = CD; c0 = b * 32; r0 = a * 32;
    }
    __shared__ float t[32][33];
    const int tx = threadIdx.x & 31, ty = threadIdx.x >> 5;
    #pragma unroll
    for (int p = 0; p < 4; p++)
        t[ty + p * 8][tx] = src[(size_t)(r0 + ty + p * 8) * C + c0 + tx];
    __syncthreads();
    #pragma unroll
    for (int p = 0; p < 4; p++)
        dst[(size_t)(c0 + ty + p * 8) * R + r0 + tx] = __float2half_rn(t[tx][ty + p * 8]);
}

// SMEM: A [128][72]h, B [128][72]h per stage, 3 stages
#define STH 72
#define STW 36
#define ROWB 144
#define A_ST_B (128 * ROWB)
#define STAGE_B (2 * A_ST_B)
#define NSTAGE 3
#define GEMM_SMEM (NSTAGE * STAGE_B)

// ============ fp16 GEMM core with ldmatrix ============
struct GemmAcc { float c[2][8][4]; };

__device__ __forceinline__ void gemm_mainloop(const __half* __restrict__ A,
                                              const __half* __restrict__ Wt,
                                              int K, int bm, int bn, char* sm,
                                              GemmAcc& G) {
    const int tid = threadIdx.x;
    const int warp = tid >> 5, lane = tid & 31;
    const int wy = warp >> 1, wx = warp & 1;

    #pragma unroll
    for (int i = 0; i < 2; i++)
        #pragma unroll
        for (int j = 0; j < 8; j++)
            #pragma unroll
            for (int t = 0; t < 4; t++) G.c[i][j][t] = 0.f;

    const int NC = K >> 6;
    const uint32_t sbase = smem_u32(sm);

    const int row = tid >> 1, gb = (tid & 1) * 4;
    const __half* Ab = A + (size_t)(bm + row) * K + gb * 8;
    const __half* Bb = Wt + (size_t)(bn + row) * K + gb * 8;
    const uint32_t aOff = (uint32_t)(row * ROWB + gb * 16);
    const uint32_t bOff = (uint32_t)(A_ST_B + row * ROWB + gb * 16);

    const int l7 = lane & 7;
    const uint32_t aLd = (uint32_t)(wy * 32 + ((lane >> 3) & 1) * 8 + l7) * ROWB + (lane >> 4) * 16;
    const uint32_t bLd = (uint32_t)(wx * 64 + ((lane >> 4) & 1) * 8 + l7) * ROWB + ((lane >> 3) & 1) * 16;

    #pragma unroll
    for (int s = 0; s < 2; s++) {
        const uint32_t st = sbase + s * STAGE_B;
        #pragma unroll
        for (int p = 0; p < 4; p++) cp16(st + aOff + p * 16, Ab + s * 64 + p * 8);
        #pragma unroll
        for (int p = 0; p < 4; p++) cp16(st + bOff + p * 16, Bb + s * 64 + p * 8);
        CP_COMMIT();
    }

    int s = 0;
    for (int c = 0; c < NC; c++) {
        CP_WAIT1();
        __syncthreads();
        if (c + 2 < NC) {
            const int s2 = (s + 2 >= NSTAGE) ? s + 2 - NSTAGE : s + 2;
            const uint32_t st = sbase + s2 * STAGE_B;
            #pragma unroll
            for (int p = 0; p < 4; p++) cp16(st + aOff + p * 16, Ab + (c + 2) * 64 + p * 8);
            #pragma unroll
            for (int p = 0; p < 4; p++) cp16(st + bOff + p * 16, Bb + (c + 2) * 64 + p * 8);
        }
        CP_COMMIT();

        const uint32_t aBase = sbase + s * STAGE_B + aLd;
        const uint32_t bBase = sbase + s * STAGE_B + A_ST_B + bLd;
        #pragma unroll
        for (int ks = 0; ks < 4; ks++) {
            uint32_t af[2][4], bf[4][4];
            ldsm4(af[0], aBase + ks * 32);
            ldsm4(af[1], aBase + 16 * ROWB + ks * 32);
            #pragma unroll
            for (int p = 0; p < 4; p++) ldsm4(bf[p], bBase + p * 16 * ROWB + ks * 32);
            #pragma unroll
            for (int i = 0; i < 2; i++)
                #pragma unroll
                for (int j = 0; j < 8; j++)
                    mma_f16(G.c[i][j], af[i], &bf[j >> 1][(j & 1) * 2]);
        }
        s = (s + 1 >= NSTAGE) ? 0 : s + 1;
    }
}

// ============ GEMM kernels ============
template <int EPI>
__global__ __launch_bounds__(256, 2) void gemm_f16(const __half* __restrict__ A,
                                                   const __half* __restrict__ Wt,
                                                   const float* __restrict__ R,
                                                   void* __restrict__ OutV,
                                                   int N, int K) {
    extern __shared__ char sm[];
    const int bm = blockIdx.y * 128, bn = blockIdx.x * 128;
    GemmAcc G;
    gemm_mainloop(A, Wt, K, bm, bn, sm, G);

    const int tid = threadIdx.x;
    const int warp = tid >> 5, lane = tid & 31;
    const int wy = warp >> 1, wx = warp & 1;
    const int gid = lane >> 2, tig = lane & 3;

    #pragma unroll
    for (int i = 0; i < 2; i++) {
        const int r0 = bm + wy * 32 + i * 16 + gid;
        const int r1 = r0 + 8;
        #pragma unroll
        for (int j = 0; j < 8; j++) {
            const int cc = bn + wx * 64 + j * 8 + 2 * tig;
            float v0 = G.c[i][j][0], v1 = G.c[i][j][1];
            float v2 = G.c[i][j][2], v3 = G.c[i][j][3];
            if (EPI == 1) {
                float* Out = (float*)OutV;
                float2 t0 = *(const float2*)(R + (size_t)r0 * N + cc);
                float2 t1 = *(const float2*)(R + (size_t)r1 * N + cc);
                *(float2*)(Out + (size_t)r0 * N + cc) = make_float2(v0 + t0.x, v1 + t0.y);
                *(float2*)(Out + (size_t)r1 * N + cc) = make_float2(v2 + t1.x, v3 + t1.y);
            } else {
                __half* Out = (__half*)OutV;
                v0 = fmaxf(v0, 0.f); v1 = fmaxf(v1, 0.f);
                v2 = fmaxf(v2, 0.f); v3 = fmaxf(v3, 0.f);
                *(uint32_t*)(Out + (size_t)r0 * N + cc) = packh2(v0 * v0, v1 * v1);
                *(uint32_t*)(Out + (size_t)r1 * N + cc) = packh2(v2 * v2, v3 * v3);
            }
        }
    }
}

// ============ fused QKV GEMM + RoPE (q pre-scaled by 0.125*log2e) ============
__global__ __launch_bounds__(256, 2) void qkv_gemm(const __half* __restrict__ A,
                                                   const __half* __restrict__ wqt,
                                                   const __half* __restrict__ wkt,
                                                   const __half* __restrict__ wvt,
                                                   const float* __restrict__ cs,
                                                   const float* __restrict__ sn,
                                                   __half* __restrict__ q,
                                                   __half* __restrict__ k,
                                                   __half* __restrict__ v) {
    extern __shared__ char sm[];
    const int mat = blockIdx.x / 6;
    const int bn = (blockIdx.x % 6) * 128;
    const int bm = blockIdx.y * 128;
    const __half* Wt = (mat == 0) ? wqt : (mat == 1) ? wkt : wvt;
    __half* Out = (mat == 0) ? q : (mat == 1) ? k : v;
    const float sc = (mat == 0) ? 0.125f * LOG2E : 1.0f;

    GemmAcc G;
    gemm_mainloop(A, Wt, CD, bm, bn, sm, G);

    const int tid = threadIdx.x;
    const int warp = tid >> 5, lane = tid & 31;
    const int wy = warp >> 1, wx = warp & 1;
    const int gid = lane >> 2, tig = lane & 3;

    if (mat == 2) {
        #pragma unroll
        for (int i = 0; i < 2; i++) {
            const int r0 = bm + wy * 32 + i * 16 + gid;
            const int r1 = r0 + 8;
            #pragma unroll
            for (int j = 0; j < 8; j++) {
                const int cc = bn + wx * 64 + j * 8 + 2 * tig;
                *(uint32_t*)(Out + (size_t)r0 * CD + cc) = packh2(G.c[i][j][0], G.c[i][j][1]);
                *(uint32_t*)(Out + (size_t)r1 * CD + cc) = packh2(G.c[i][j][2], G.c[i][j][3]);
            }
        }
    } else {
        #pragma unroll
        for (int i = 0; i < 2; i++) {
            const int r0 = bm + wy * 32 + i * 16 + gid;
            const int r1 = r0 + 8;
            const int t0 = r0 & (TT - 1), t1 = r1 & (TT - 1);
            #pragma unroll
            for (int j = 0; j < 4; j++) {
                const int d = j * 8 + 2 * tig;
                const int cc = bn + wx * 64 + j * 8 + 2 * tig;
                float2 c0 = *(const float2*)(cs + t0 * DD2 + d);
                float2 s0 = *(const float2*)(sn + t0 * DD2 + d);
                float2 c1 = *(const float2*)(cs + t1 * DD2 + d);
                float2 s1 = *(const float2*)(sn + t1 * DD2 + d);
                float x1a = G.c[i][j][0], x1b = G.c[i][j][1];
                float x2a = G.c[i][j + 4][0], x2b = G.c[i][j + 4][1];
                *(uint32_t*)(Out + (size_t)r0 * CD + cc) =
                    packh2(sc * (x1a * c0.x + x2a * s0.x), sc * (x1b * c0.y + x2b * s0.y));
                *(uint32_t*)(Out + (size_t)r0 * CD + cc + 32) =
                    packh2(sc * (-x1a * s0.x + x2a * c0.x), sc * (-x1b * s0.y + x2b * c0.y));
                float y1a = G.c[i][j][2], y1b = G.c[i][j][3];
                float y2a = G.c[i][j + 4][2], y2b = G.c[i][j + 4][3];
                *(uint32_t*)(Out + (size_t)r1 * CD + cc) =
                    packh2(sc * (y1a * c1.x + y2a * s1.x), sc * (y1b * c1.y + y2b * s1.y));
                *(uint32_t*)(Out + (size_t)r1 * CD + cc + 32) =
                    packh2(sc * (-y1a * s1.x + y2a * c1.x), sc * (-y1b * s1.y + y2b * c1.y));
            }
        }
    }
}

// ---------------- RMSNorm: f32 in, half out ----------------
__global__ __launch_bounds__(256) void rmsnorm_kernel(const float* __restrict__ x,
                                                      const float* __restrict__ g,
                                                      __half* __restrict__ out) {
    int row = blockIdx.x;
    const float* xr = x + (size_t)row * CD;
    float ss = 0.f;
    for (int i = threadIdx.x; i < CD; i += 256) { float v = xr[i]; ss += v * v; }
    #pragma unroll
    for (int o = 16; o; o >>= 1) ss += __shfl_xor_sync(0xffffffffu, ss, o);
    __shared__ float red[8];
    if ((threadIdx.x & 31) == 0) red[threadIdx.x >> 5] = ss;
    __syncthreads();
    float tot = 0.f;
    #pragma unroll
    for (int i = 0; i < 8; i++) tot += red[i];
    float rinv = rsqrtf(tot / (float)CD + kEPS);
    __half* orow = out + (size_t)row * CD;
    for (int i = threadIdx.x; i < CD; i += 256) orow[i] = __float2half_rn(g[i] * xr[i] * rinv);
}

// ---------------- fp16 Flash Attention: 128 q-rows, 8 warps, P in registers ----------------
#define KV_H (64 * STH)
#define ATTN_SMEM ((128 * STH + 4 * KV_H) * 2)   // 55296 B
__global__ __launch_bounds__(256, 2) void attn_f16(const __half* __restrict__ q,
                                                   const __half* __restrict__ k,
                                                   const __half* __restrict__ v,
                                                   __half* __restrict__ y) {
    extern __shared__ char asmc[];
    __half* uQ = (__half*)asmc;

    const int h = blockIdx.y, b = blockIdx.z;
    const int qtb = (int)gridDim.x - 1 - (int)blockIdx.x;   // big tiles first
    const int tid = threadIdx.x, warp = tid >> 5, lane = tid & 31;
    const int gid = lane >> 2, tig = lane & 3;
    const int qs = qtb * 128;
    const size_t bh = (size_t)b * TT * CD + (size_t)h * HDIM;

    const uint32_t sQ = smem_u32(uQ);
    const uint32_t kvBase[2] = { sQ + 128 * ROWB, sQ + 128 * ROWB + 2 * KV_H * 2 };
    const int l7 = lane & 7;
    const uint32_t aLd = (uint32_t)(((lane >> 3) & 1) * 8 + l7) * ROWB + (lane >> 4) * 16;
    const uint32_t bLd = (uint32_t)(((lane >> 4) & 1) * 8 + l7) * ROWB + ((lane >> 3) & 1) * 16;
    const uint32_t vLd = (uint32_t)(((lane >> 3) & 1) * 8 + l7) * ROWB + ((lane >> 4) & 1) * 16;

    // stage Q (pre-scaled by 0.125*log2e at QKV epilogue)
    for (int i = tid; i < 128 * 8; i += 256) {
        const int r = i >> 3, g = i & 7;
        *(uint4*)((char*)uQ + r * ROWB + g * 16) =
            *(const uint4*)(q + bh + (size_t)(qs + r) * CD + g * 8);
    }
    __syncthreads();

    uint32_t qf[4][4];
    #pragma unroll
    for (int kb = 0; kb < 4; kb++)
        ldsm4(qf[kb], sQ + (uint32_t)(warp * 16) * ROWB + aLd + kb * 32);

    float m[2] = {-1e30f, -1e30f}, l[2] = {0.f, 0.f};
    float o[8][4];
    #pragma unroll
    for (int j = 0; j < 8; j++)
        #pragma unroll
        for (int t = 0; t < 4; t++) o[j][t] = 0.f;

    const int qrow0 = qs + warp * 16;
    const int nk = 2 * qtb + 2;

    // prologue: stage KV tile 0
    {
        const int r = tid >> 3, g = tid & 7;
        #pragma unroll
        for (int p = 0; p < 2; p++) {
            const int rr = r + p * 32;
            cp16(kvBase[0] + rr * ROWB + g * 16, k + bh + (size_t)rr * CD + g * 8);
            cp16(kvBase[0] + KV_H * 2 + rr * ROWB + g * 16, v + bh + (size_t)rr * CD + g * 8);
        }
        CP_COMMIT();
    }

    for (int kt = 0; kt < nk; kt++) {
        CP_WAIT0();
        __syncthreads();
        if (kt + 1 < nk) {
            const uint32_t dstb = kvBase[(kt + 1) & 1];
            const int ks1 = (kt + 1) * 64;
            const int r = tid >> 3, g = tid & 7;
            #pragma unroll
            for (int p = 0; p < 2; p++) {
                const int rr = r + p * 32;
                cp16(dstb + rr * ROWB + g * 16, k + bh + (size_t)(ks1 + rr) * CD + g * 8);
                cp16(dstb + KV_H * 2 + rr * ROWB + g * 16, v + bh + (size_t)(ks1 + rr) * CD + g * 8);
            }
        }
        CP_COMMIT();

        const int ks = kt * 64;
        const uint32_t sK = kvBase[kt & 1];
        const uint32_t sV = sK + KV_H * 2;

        // S = Q K^T
        float sf[8][4];
        #pragma unroll
        for (int j = 0; j < 8; j++)
            #pragma unroll
            for (int t = 0; t < 4; t++) sf[j][t] = 0.f;
        #pragma unroll
        for (int kb = 0; kb < 4; kb++) {
            uint32_t bf[4][4];
            #pragma unroll
            for (int p = 0; p < 4; p++)
                ldsm4(bf[p], sK + (uint32_t)(p * 16) * ROWB + bLd + kb * 32);
            #pragma unroll
            for (int j = 0; j < 8; j++)
                mma_f16(sf[j], qf[kb], &bf[j >> 1][(j & 1) * 2]);
        }

        // causal mask when tile crosses the diagonal
        if (ks + 63 > qrow0) {
            const int qr0 = qrow0 + gid, qr1 = qr0 + 8;
            #pragma unroll
            for (int j = 0; j < 8; j++) {
                const int kc = ks + j * 8 + 2 * tig;
                if (kc > qr0)     sf[j][0] = -1e30f;
                if (kc + 1 > qr0) sf[j][1] = -1e30f;
                if (kc > qr1)     sf[j][2] = -1e30f;
                if (kc + 1 > qr1) sf[j][3] = -1e30f;
            }
        }

        // online softmax (base-2; scale folded into q)
        #pragma unroll
        for (int r = 0; r < 2; r++) {
            float mx = -1e30f;
            #pragma unroll
            for (int j = 0; j < 8; j++)
                mx = fmaxf(mx, fmaxf(sf[j][2 * r], sf[j][2 * r + 1]));
            mx = fmaxf(mx, __shfl_xor_sync(0xffffffffu, mx, 1));
            mx = fmaxf(mx, __shfl_xor_sync(0xffffffffu, mx, 2));
            const float mnew = fmaxf(m[r], mx);
            const float alpha = exp2f(m[r] - mnew);
            float rs = 0.f;
            #pragma unroll
            for (int j = 0; j < 8; j++) {
                float p0 = exp2f(sf[j][2 * r] - mnew);
                float p1 = exp2f(sf[j][2 * r + 1] - mnew);
                sf[j][2 * r] = p0; sf[j][2 * r + 1] = p1;
                rs += p0 + p1;
            }
            rs += __shfl_xor_sync(0xffffffffu, rs, 1);
            rs += __shfl_xor_sync(0xffffffffu, rs, 2);
            l[r] = l[r] * alpha + rs;
            m[r] = mnew;
            #pragma unroll
            for (int j = 0; j < 8; j++) { o[j][2 * r] *= alpha; o[j][2 * r + 1] *= alpha; }
        }

        // O += P V : P fragments built DIRECTLY from S C-fragments (no smem round-trip).
        // A-frag for chunk kb: {(gid, 16kb+2tig), (gid+8, same), (gid, 16kb+8+2tig), (gid+8, same)}
        //  = {pack(sf[2kb][0,1]), pack(sf[2kb][2,3]), pack(sf[2kb+1][0,1]), pack(sf[2kb+1][2,3])}
        #pragma unroll
        for (int kb = 0; kb < 4; kb++) {
            uint32_t pa[4];
            pa[0] = packh2(sf[2 * kb][0],     sf[2 * kb][1]);
            pa[1] = packh2(sf[2 * kb][2],     sf[2 * kb][3]);
            pa[2] = packh2(sf[2 * kb + 1][0], sf[2 * kb + 1][1]);
            pa[3] = packh2(sf[2 * kb + 1][2], sf[2 * kb + 1][3]);
            uint32_t vf[4][4];
            #pragma unroll
            for (int p = 0; p < 4; p++)
                ldsm4t(vf[p], sV + (uint32_t)(kb * 16) * ROWB + vLd + p * 32);
            #pragma unroll
            for (int j = 0; j < 8; j++)
                mma_f16(o[j], pa, &vf[j >> 1][(j & 1) * 2]);
        }
    }

    const float inv0 = 1.f / l[0], inv1 = 1.f / l[1];
    const int qa0 = qs + warp * 16 + gid, qa1 = qa0 + 8;
    #pragma unroll
    for (int j = 0; j < 8; j++) {
        const int cc = j * 8 + 2 * tig;
        *(uint32_t*)(y + bh + (size_t)qa0 * CD + cc) = packh2(o[j][0] * inv0, o[j][1] * inv0);
        *(uint32_t*)(y + bh + (size_t)qa1 * CD + cc) = packh2(o[j][2] * inv1, o[j][3] * inv1);
    }
}

// ---------------- launch ----------------
extern "C" void kernel_launch(void* const* d_in, const int* in_sizes, int n_in,
                              void* d_out, int out_size) {
    const float* x   = (const float*)d_in[0];
    const float* cs  = (const float*)d_in[1];
    const float* sn  = (const float*)d_in[2];
    const float* wq  = (const float*)d_in[3];
    const float* wk  = (const float*)d_in[4];
    const float* wv  = (const float*)d_in[5];
    const float* wo  = (const float*)d_in[6];
    const float* wfc = (const float*)d_in[7];
    const float* wpr = (const float*)d_in[8];
    const float* g1  = (const float*)d_in[9];
    const float* g2  = (const float*)d_in[10];
    float* out = (float*)d_out;

    __half *h, *q, *k, *v, *y, *ff;
    __half *wqt, *wkt, *wvt, *wot, *wfct, *wprt;
    float *x2;
    cudaGetSymbolAddress((void**)&h,  g_h);
    cudaGetSymbolAddress((void**)&q,  g_q);
    cudaGetSymbolAddress((void**)&k,  g_k);
    cudaGetSymbolAddress((void**)&v,  g_v);
    cudaGetSymbolAddress((void**)&y,  g_y);
    cudaGetSymbolAddress((void**)&ff, g_ff);
    cudaGetSymbolAddress((void**)&x2, g_x2);
    cudaGetSymbolAddress((void**)&wqt,  g_wqt);
    cudaGetSymbolAddress((void**)&wkt,  g_wkt);
    cudaGetSymbolAddress((void**)&wvt,  g_wvt);
    cudaGetSymbolAddress((void**)&wot,  g_wot);
    cudaGetSymbolAddress((void**)&wfct, g_wfct);
    cudaGetSymbolAddress((void**)&wprt, g_wprt);

    cudaFuncSetAttribute((const void*)attn_f16,
                         cudaFuncAttributeMaxDynamicSharedMemorySize, ATTN_SMEM);
    cudaFuncSetAttribute((const void*)qkv_gemm,
                         cudaFuncAttributeMaxDynamicSharedMemorySize, GEMM_SMEM);
    cudaFuncSetAttribute((const void*)gemm_f16<1>,
                         cudaFuncAttributeMaxDynamicSharedMemorySize, GEMM_SMEM);
    cudaFuncSetAttribute((const void*)gemm_f16<2>,
                         cudaFuncAttributeMaxDynamicSharedMemorySize, GEMM_SMEM);

    // 0. batched transpose+convert
    transp_all<<<dim3(96, 24, 6), 256>>>(wq, wk, wv, wo, wfc, wpr,
                                         wqt, wkt, wvt, wot, wfct, wprt);

    // 1. h = rmsnorm(x, g1)
    rmsnorm_kernel<<<NROWS, 256>>>(x, g1, h);

    // 2+3. q,k,v with RoPE fused, q pre-scaled
    qkv_gemm<<<dim3(18, 32), 256, GEMM_SMEM>>>(h, wqt, wkt, wvt, cs, sn, q, k, v);

    // 4. attention -> y
    attn_f16<<<dim3(TT / 128, HH, BB), 256, ATTN_SMEM>>>(q, k, v, y);

    // 5. x2 = x + y @ wo
    dim3 gCC(CD / 128, NROWS / 128);
    gemm_f16<1><<<gCC, 256, GEMM_SMEM>>>(y, wot, x, x2, CD, CD);

    // 6. h = rmsnorm(x2, g2)
    rmsnorm_kernel<<<NROWS, 256>>>(x2, g2, h);

    // 7. ff = relu(h @ wfc)^2
    dim3 gFC(FFD / 128, NROWS / 128);
    gemm_f16<2><<<gFC, 256, GEMM_SMEM>>>(h, wfct, nullptr, ff, FFD, CD);

    // 8. out = x2 + ff @ wpr
    gemm_f16<1><<<gCC, 256, GEMM_SMEM>>>(ff, wprt, x2, out, CD, FFD);
}

// round 11
// speedup vs baseline: 1.9663x; 1.0355x over previous
#include <cuda_runtime.h>
#include <cuda_fp16.h>
#include <math.h>
#include <stdint.h>

// Problem constants
#define BB 2
#define TT 2048
#define CD 768
#define HH 12
#define HDIM 64
#define DD2 32
#define FFD 3072
#define NROWS (BB*TT)          // 4096
static __device__ __constant__ float kEPS = 1e-5f;
#define LOG2E 1.44269504088896340736f

// ---------------- scratch ----------------
__device__ __half g_h [NROWS*CD];
__device__ __half g_q [NROWS*CD];
__device__ __half g_k [NROWS*CD];
__device__ __half g_v [NROWS*CD];
__device__ __half g_y [NROWS*CD];
__device__ __half g_ff[NROWS*FFD];
__device__ float  g_x2[NROWS*CD];
__device__ __half g_wqt [CD*CD];
__device__ __half g_wkt [CD*CD];
__device__ __half g_wvt [CD*CD];
__device__ __half g_wot [CD*CD];
__device__ __half g_wfct[FFD*CD];
__device__ __half g_wprt[CD*FFD];

// ---------------- helpers ----------------
__device__ __forceinline__ void mma_f16(float* c, const uint32_t* a, const uint32_t* b) {
    asm volatile(
        "mma.sync.aligned.m16n8k16.row.col.f32.f16.f16.f32 "
        "{%0,%1,%2,%3}, {%4,%5,%6,%7}, {%8,%9}, {%0,%1,%2,%3};"
        : "+f"(c[0]), "+f"(c[1]), "+f"(c[2]), "+f"(c[3])
        : "r"(a[0]), "r"(a[1]), "r"(a[2]), "r"(a[3]), "r"(b[0]), "r"(b[1]));
}
__device__ __forceinline__ void ldsm4(uint32_t* r, uint32_t addr) {
    asm volatile("ldmatrix.sync.aligned.m8n8.x4.shared.b16 {%0,%1,%2,%3}, [%4];"
                 : "=r"(r[0]), "=r"(r[1]), "=r"(r[2]), "=r"(r[3]) : "r"(addr));
}
__device__ __forceinline__ void ldsm4t(uint32_t* r, uint32_t addr) {
    asm volatile("ldmatrix.sync.aligned.m8n8.x4.trans.shared.b16 {%0,%1,%2,%3}, [%4];"
                 : "=r"(r[0]), "=r"(r[1]), "=r"(r[2]), "=r"(r[3]) : "r"(addr));
}
__device__ __forceinline__ uint32_t smem_u32(const void* p) {
    uint32_t a;
    asm("{ .reg .u64 t; cvta.to.shared.u64 t, %1; cvt.u32.u64 %0, t; }" : "=r"(a) : "l"(p));
    return a;
}
__device__ __forceinline__ void cp16(uint32_t dst, const void* src) {
    asm volatile("cp.async.cg.shared.global [%0], [%1], 16;" :: "r"(dst), "l"(src));
}
#define CP_COMMIT() asm volatile("cp.async.commit_group;" ::: "memory")
#define CP_WAIT1()  asm volatile("cp.async.wait_group 1;" ::: "memory")
#define CP_WAIT0()  asm volatile("cp.async.wait_group 0;" ::: "memory")
__device__ __forceinline__ uint32_t packh2(float a, float b) {
    __half2 h = __floats2half2_rn(a, b);
    return *(uint32_t*)&h;
}

// ---------------- batched weight transpose+convert ----------------
__global__ __launch_bounds__(256) void transp_all(
    const float* __restrict__ wq, const float* __restrict__ wk,
    const float* __restrict__ wv, const float* __restrict__ wo,
    const float* __restrict__ wfc, const float* __restrict__ wpr,
    __half* __restrict__ wqt, __half* __restrict__ wkt,
    __half* __restrict__ wvt, __half* __restrict__ wot,
    __half* __restrict__ wfct, __half* __restrict__ wprt) {
    const int z = blockIdx.z, a = blockIdx.x, b = blockIdx.y;
    const float* src; __half* dst; int R, C, c0, r0;
    if (z < 4) {
        if (a >= 24) return;
        src = (z == 0) ? wq : (z == 1) ? wk : (z == 2) ? wv : wo;
        dst = (z == 0) ? wqt : (z == 1) ? wkt : (z == 2) ? wvt : wot;
        R = CD; C = CD; c0 = a * 32; r0 = b * 32;
    } else if (z == 4) {
        src = wfc; dst = wfct; R = CD; C = FFD; c0 = a * 32; r0 = b * 32;
    } else {
        src = wpr; dst = wprt; R = FFD; C = CD; c0 = b * 32; r0 = a * 32;
    }
    __shared__ float t[32][33];
    const int tx = threadIdx.x & 31, ty = threadIdx.x >> 5;
    #pragma unroll
    for (int p = 0; p < 4; p++)
        t[ty + p * 8][tx] = src[(size_t)(r0 + ty + p * 8) * C + c0 + tx];
    __syncthreads();
    #pragma unroll
    for (int p = 0; p < 4; p++)
        dst[(size_t)(c0 + ty + p * 8) * R + r0 + tx] = __float2half_rn(t[tx][ty + p * 8]);
}

// SMEM geometry
#define STH 72
#define STW 36
#define ROWB 144
#define A_ST_B (128 * ROWB)             // 18432
#define STAGE_B (2 * A_ST_B)            // 36864 (BN=128)
#define NSTAGE 3
#define GEMM_SMEM (NSTAGE * STAGE_B)    // 110592
#define B64_ST_B (64 * ROWB)            // 9216
#define STAGE64_B (A_ST_B + B64_ST_B)   // 27648
#define GEMM64_SMEM (NSTAGE * STAGE64_B) // 82944

// ============ fp16 GEMM core BN=128: 256 thr, warp tile 32x64 ============
struct GemmAcc { float c[2][8][4]; };

__device__ __forceinline__ void gemm_mainloop(const __half* __restrict__ A,
                                              const __half* __restrict__ Wt,
                                              int K, int bm, int bn, char* sm,
                                              GemmAcc& G) {
    const int tid = threadIdx.x;
    const int warp = tid >> 5, lane = tid & 31;
    const int wy = warp >> 1, wx = warp & 1;

    #pragma unroll
    for (int i = 0; i < 2; i++)
        #pragma unroll
        for (int j = 0; j < 8; j++)
            #pragma unroll
            for (int t = 0; t < 4; t++) G.c[i][j][t] = 0.f;

    const int NC = K >> 6;
    const uint32_t sbase = smem_u32(sm);

    const int row = tid >> 1, gb = (tid & 1) * 4;
    const __half* Ab = A + (size_t)(bm + row) * K + gb * 8;
    const __half* Bb = Wt + (size_t)(bn + row) * K + gb * 8;
    const uint32_t aOff = (uint32_t)(row * ROWB + gb * 16);
    const uint32_t bOff = (uint32_t)(A_ST_B + row * ROWB + gb * 16);

    const int l7 = lane & 7;
    const uint32_t aLd = (uint32_t)(wy * 32 + ((lane >> 3) & 1) * 8 + l7) * ROWB + (lane >> 4) * 16;
    const uint32_t bLd = (uint32_t)(wx * 64 + ((lane >> 4) & 1) * 8 + l7) * ROWB + ((lane >> 3) & 1) * 16;

    #pragma unroll
    for (int s = 0; s < 2; s++) {
        const uint32_t st = sbase + s * STAGE_B;
        #pragma unroll
        for (int p = 0; p < 4; p++) cp16(st + aOff + p * 16, Ab + s * 64 + p * 8);
        #pragma unroll
        for (int p = 0; p < 4; p++) cp16(st + bOff + p * 16, Bb + s * 64 + p * 8);
        CP_COMMIT();
    }

    int s = 0;
    for (int c = 0; c < NC; c++) {
        CP_WAIT1();
        __syncthreads();
        if (c + 2 < NC) {
            const int s2 = (s + 2 >= NSTAGE) ? s + 2 - NSTAGE : s + 2;
            const uint32_t st = sbase + s2 * STAGE_B;
            #pragma unroll
            for (int p = 0; p < 4; p++) cp16(st + aOff + p * 16, Ab + (c + 2) * 64 + p * 8);
            #pragma unroll
            for (int p = 0; p < 4; p++) cp16(st + bOff + p * 16, Bb + (c + 2) * 64 + p * 8);
        }
        CP_COMMIT();

        const uint32_t aBase = sbase + s * STAGE_B + aLd;
        const uint32_t bBase = sbase + s * STAGE_B + A_ST_B + bLd;
        #pragma unroll
        for (int ks = 0; ks < 4; ks++) {
            uint32_t af[2][4], bf[4][4];
            ldsm4(af[0], aBase + ks * 32);
            ldsm4(af[1], aBase + 16 * ROWB + ks * 32);
            #pragma unroll
            for (int p = 0; p < 4; p++) ldsm4(bf[p], bBase + p * 16 * ROWB + ks * 32);
            #pragma unroll
            for (int i = 0; i < 2; i++)
                #pragma unroll
                for (int j = 0; j < 8; j++)
                    mma_f16(G.c[i][j], af[i], &bf[j >> 1][(j & 1) * 2]);
        }
        s = (s + 1 >= NSTAGE) ? 0 : s + 1;
    }
}

// ============ fp16 GEMM core BN=64: 256 thr, warp tile 32x32 ============
__device__ __forceinline__ void gemm_mainloop64(const __half* __restrict__ A,
                                                const __half* __restrict__ Wt,
                                                int K, int bm, int bn, char* sm,
                                                float c64[2][4][4]) {
    const int tid = threadIdx.x;
    const int warp = tid >> 5, lane = tid & 31;
    const int wy = warp >> 1, wx = warp & 1;

    #pragma unroll
    for (int i = 0; i < 2; i++)
        #pragma unroll
        for (int j = 0; j < 4; j++)
            #pragma unroll
            for (int t = 0; t < 4; t++) c64[i][j][t] = 0.f;

    const int NC = K >> 6;
    const uint32_t sbase = smem_u32(sm);

    // A staging: 2 threads/row, 4 granules each
    const int rowA = tid >> 1, gA = (tid & 1) * 4;
    const __half* Ab = A + (size_t)(bm + rowA) * K + gA * 8;
    const uint32_t aOff = (uint32_t)(rowA * ROWB + gA * 16);
    // B staging: 4 threads/row (64 rows), 2 granules each
    const int rowB = tid >> 2, gB = (tid & 3) * 2;
    const __half* Bb = Wt + (size_t)(bn + rowB) * K + gB * 8;
    const uint32_t bOff = (uint32_t)(A_ST_B + rowB * ROWB + gB * 16);

    const int l7 = lane & 7;
    const uint32_t aLd = (uint32_t)(wy * 32 + ((lane >> 3) & 1) * 8 + l7) * ROWB + (lane >> 4) * 16;
    const uint32_t bLd = (uint32_t)(wx * 32 + ((lane >> 4) & 1) * 8 + l7) * ROWB + ((lane >> 3) & 1) * 16;

    #pragma unroll
    for (int s = 0; s < 2; s++) {
        const uint32_t st = sbase + s * STAGE64_B;
        #pragma unroll
        for (int p = 0; p < 4; p++) cp16(st + aOff + p * 16, Ab + s * 64 + p * 8);
        #pragma unroll
        for (int p = 0; p < 2; p++) cp16(st + bOff + p * 16, Bb + s * 64 + p * 8);
        CP_COMMIT();
    }

    int s = 0;
    for (int c = 0; c < NC; c++) {
        CP_WAIT1();
        __syncthreads();
        if (c + 2 < NC) {
            const int s2 = (s + 2 >= NSTAGE) ? s + 2 - NSTAGE : s + 2;
            const uint32_t st = sbase + s2 * STAGE64_B;
            #pragma unroll
            for (int p = 0; p < 4; p++) cp16(st + aOff + p * 16, Ab + (c + 2) * 64 + p * 8);
            #pragma unroll
            for (int p = 0; p < 2; p++) cp16(st + bOff + p * 16, Bb + (c + 2) * 64 + p * 8);
        }
        CP_COMMIT();

        const uint32_t aBase = sbase + s * STAGE64_B + aLd;
        const uint32_t bBase = sbase + s * STAGE64_B + A_ST_B + bLd;
        #pragma unroll
        for (int ks = 0; ks < 4; ks++) {
            uint32_t af[2][4], bf[2][4];
            ldsm4(af[0], aBase + ks * 32);
            ldsm4(af[1], aBase + 16 * ROWB + ks * 32);
            #pragma unroll
            for (int p = 0; p < 2; p++) ldsm4(bf[p], bBase + p * 16 * ROWB + ks * 32);
            #pragma unroll
            for (int i = 0; i < 2; i++)
                #pragma unroll
                for (int j = 0; j < 4; j++)
                    mma_f16(c64[i][j], af[i], &bf[j >> 1][(j & 1) * 2]);
        }
        s = (s + 1 >= NSTAGE) ? 0 : s + 1;
    }
}

// ============ GEMM kernels ============
// EPI 1: f32 out = acc + R.  EPI 2: half out = relu(acc)^2.
template <int EPI>
__global__ __launch_bounds__(256, 2) void gemm_f16(const __half* __restrict__ A,
                                                   const __half* __restrict__ Wt,
                                                   const float* __restrict__ R,
                                                   void* __restrict__ OutV,
                                                   int N, int K) {
    extern __shared__ char sm[];
    const int bm = blockIdx.y * 128, bn = blockIdx.x * 128;
    GemmAcc G;
    gemm_mainloop(A, Wt, K, bm, bn, sm, G);

    const int tid = threadIdx.x;
    const int warp = tid >> 5, lane = tid & 31;
    const int wy = warp >> 1, wx = warp & 1;
    const int gid = lane >> 2, tig = lane & 3;

    #pragma unroll
    for (int i = 0; i < 2; i++) {
        const int r0 = bm + wy * 32 + i * 16 + gid;
        const int r1 = r0 + 8;
        #pragma unroll
        for (int j = 0; j < 8; j++) {
            const int cc = bn + wx * 64 + j * 8 + 2 * tig;
            float v0 = G.c[i][j][0], v1 = G.c[i][j][1];
            float v2 = G.c[i][j][2], v3 = G.c[i][j][3];
            if (EPI == 1) {
                float* Out = (float*)OutV;
                float2 t0 = *(const float2*)(R + (size_t)r0 * N + cc);
                float2 t1 = *(const float2*)(R + (size_t)r1 * N + cc);
                *(float2*)(Out + (size_t)r0 * N + cc) = make_float2(v0 + t0.x, v1 + t0.y);
                *(float2*)(Out + (size_t)r1 * N + cc) = make_float2(v2 + t1.x, v3 + t1.y);
            } else {
                __half* Out = (__half*)OutV;
                v0 = fmaxf(v0, 0.f); v1 = fmaxf(v1, 0.f);
                v2 = fmaxf(v2, 0.f); v3 = fmaxf(v3, 0.f);
                *(uint32_t*)(Out + (size_t)r0 * N + cc) = packh2(v0 * v0, v1 * v1);
                *(uint32_t*)(Out + (size_t)r1 * N + cc) = packh2(v2 * v2, v3 * v3);
            }
        }
    }
}

template <int EPI>
__global__ __launch_bounds__(256, 2) void gemm64_f16(const __half* __restrict__ A,
                                                     const __half* __restrict__ Wt,
                                                     const float* __restrict__ R,
                                                     void* __restrict__ OutV,
                                                     int N, int K) {
    extern __shared__ char sm[];
    const int bm = blockIdx.y * 128, bn = blockIdx.x * 64;
    float c64[2][4][4];
    gemm_mainloop64(A, Wt, K, bm, bn, sm, c64);

    const int tid = threadIdx.x;
    const int warp = tid >> 5, lane = tid & 31;
    const int wy = warp >> 1, wx = warp & 1;
    const int gid = lane >> 2, tig = lane & 3;

    #pragma unroll
    for (int i = 0; i < 2; i++) {
        const int r0 = bm + wy * 32 + i * 16 + gid;
        const int r1 = r0 + 8;
        #pragma unroll
        for (int j = 0; j < 4; j++) {
            const int cc = bn + wx * 32 + j * 8 + 2 * tig;
            float v0 = c64[i][j][0], v1 = c64[i][j][1];
            float v2 = c64[i][j][2], v3 = c64[i][j][3];
            if (EPI == 1) {
                float* Out = (float*)OutV;
                float2 t0 = *(const float2*)(R + (size_t)r0 * N + cc);
                float2 t1 = *(const float2*)(R + (size_t)r1 * N + cc);
                *(float2*)(Out + (size_t)r0 * N + cc) = make_float2(v0 + t0.x, v1 + t0.y);
                *(float2*)(Out + (size_t)r1 * N + cc) = make_float2(v2 + t1.x, v3 + t1.y);
            } else {
                __half* Out = (__half*)OutV;
                v0 = fmaxf(v0, 0.f); v1 = fmaxf(v1, 0.f);
                v2 = fmaxf(v2, 0.f); v3 = fmaxf(v3, 0.f);
                *(uint32_t*)(Out + (size_t)r0 * N + cc) = packh2(v0 * v0, v1 * v1);
                *(uint32_t*)(Out + (size_t)r1 * N + cc) = packh2(v2 * v2, v3 * v3);
            }
        }
    }
}

// ============ fused QKV GEMM + RoPE (q pre-scaled by 0.125*log2e) ============
__global__ __launch_bounds__(256, 2) void qkv_gemm(const __half* __restrict__ A,
                                                   const __half* __restrict__ wqt,
                                                   const __half* __restrict__ wkt,
                                                   const __half* __restrict__ wvt,
                                                   const float* __restrict__ cs,
                                                   const float* __restrict__ sn,
                                                   __half* __restrict__ q,
                                                   __half* __restrict__ k,
                                                   __half* __restrict__ v) {
    extern __shared__ char sm[];
    const int mat = blockIdx.x / 6;
    const int bn = (blockIdx.x % 6) * 128;
    const int bm = blockIdx.y * 128;
    const __half* Wt = (mat == 0) ? wqt : (mat == 1) ? wkt : wvt;
    __half* Out = (mat == 0) ? q : (mat == 1) ? k : v;
    const float sc = (mat == 0) ? 0.125f * LOG2E : 1.0f;

    GemmAcc G;
    gemm_mainloop(A, Wt, CD, bm, bn, sm, G);

    const int tid = threadIdx.x;
    const int warp = tid >> 5, lane = tid & 31;
    const int wy = warp >> 1, wx = warp & 1;
    const int gid = lane >> 2, tig = lane & 3;

    if (mat == 2) {
        #pragma unroll
        for (int i = 0; i < 2; i++) {
            const int r0 = bm + wy * 32 + i * 16 + gid;
            const int r1 = r0 + 8;
            #pragma unroll
            for (int j = 0; j < 8; j++) {
                const int cc = bn + wx * 64 + j * 8 + 2 * tig;
                *(uint32_t*)(Out + (size_t)r0 * CD + cc) = packh2(G.c[i][j][0], G.c[i][j][1]);
                *(uint32_t*)(Out + (size_t)r1 * CD + cc) = packh2(G.c[i][j][2], G.c[i][j][3]);
            }
        }
    } else {
        #pragma unroll
        for (int i = 0; i < 2; i++) {
            const int r0 = bm + wy * 32 + i * 16 + gid;
            const int r1 = r0 + 8;
            const int t0 = r0 & (TT - 1), t1 = r1 & (TT - 1);
            #pragma unroll
            for (int j = 0; j < 4; j++) {
                const int d = j * 8 + 2 * tig;
                const int cc = bn + wx * 64 + j * 8 + 2 * tig;
                float2 c0 = *(const float2*)(cs + t0 * DD2 + d);
                float2 s0 = *(const float2*)(sn + t0 * DD2 + d);
                float2 c1 = *(const float2*)(cs + t1 * DD2 + d);
                float2 s1 = *(const float2*)(sn + t1 * DD2 + d);
                float x1a = G.c[i][j][0], x1b = G.c[i][j][1];
                float x2a = G.c[i][j + 4][0], x2b = G.c[i][j + 4][1];
                *(uint32_t*)(Out + (size_t)r0 * CD + cc) =
                    packh2(sc * (x1a * c0.x + x2a * s0.x), sc * (x1b * c0.y + x2b * s0.y));
                *(uint32_t*)(Out + (size_t)r0 * CD + cc + 32) =
                    packh2(sc * (-x1a * s0.x + x2a * c0.x), sc * (-x1b * s0.y + x2b * c0.y));
                float y1a = G.c[i][j][2], y1b = G.c[i][j][3];
                float y2a = G.c[i][j + 4][2], y2b = G.c[i][j + 4][3];
                *(uint32_t*)(Out + (size_t)r1 * CD + cc) =
                    packh2(sc * (y1a * c1.x + y2a * s1.x), sc * (y1b * c1.y + y2b * s1.y));
                *(uint32_t*)(Out + (size_t)r1 * CD + cc + 32) =
                    packh2(sc * (-y1a * s1.x + y2a * c1.x), sc * (-y1b * s1.y + y2b * c1.y));
            }
        }
    }
}

// ---------------- RMSNorm: f32 in, half out ----------------
__global__ __launch_bounds__(256) void rmsnorm_kernel(const float* __restrict__ x,
                                                      const float* __restrict__ g,
                                                      __half* __restrict__ out) {
    int row = blockIdx.x;
    const float* xr = x + (size_t)row * CD;
    float ss = 0.f;
    for (int i = threadIdx.x; i < CD; i += 256) { float v = xr[i]; ss += v * v; }
    #pragma unroll
    for (int o = 16; o; o >>= 1) ss += __shfl_xor_sync(0xffffffffu, ss, o);
    __shared__ float red[8];
    if ((threadIdx.x & 31) == 0) red[threadIdx.x >> 5] = ss;
    __syncthreads();
    float tot = 0.f;
    #pragma unroll
    for (int i = 0; i < 8; i++) tot += red[i];
    float rinv = rsqrtf(tot / (float)CD + kEPS);
    __half* orow = out + (size_t)row * CD;
    for (int i = threadIdx.x; i < CD; i += 256) orow[i] = __float2half_rn(g[i] * xr[i] * rinv);
}

// ---------------- fp16 Flash Attention (unchanged from R10) ----------------
#define KV_H (64 * STH)
#define ATTN_SMEM ((128 * STH + 4 * KV_H) * 2)   // 55296 B
__global__ __launch_bounds__(256, 2) void attn_f16(const __half* __restrict__ q,
                                                   const __half* __restrict__ k,
                                                   const __half* __restrict__ v,
                                                   __half* __restrict__ y) {
    extern __shared__ char asmc[];
    __half* uQ = (__half*)asmc;

    const int h = blockIdx.y, b = blockIdx.z;
    const int qtb = (int)gridDim.x - 1 - (int)blockIdx.x;   // big tiles first
    const int tid = threadIdx.x, warp = tid >> 5, lane = tid & 31;
    const int gid = lane >> 2, tig = lane & 3;
    const int qs = qtb * 128;
    const size_t bh = (size_t)b * TT * CD + (size_t)h * HDIM;

    const uint32_t sQ = smem_u32(uQ);
    const uint32_t kvBase[2] = { sQ + 128 * ROWB, sQ + 128 * ROWB + 2 * KV_H * 2 };
    const int l7 = lane & 7;
    const uint32_t aLd = (uint32_t)(((lane >> 3) & 1) * 8 + l7) * ROWB + (lane >> 4) * 16;
    const uint32_t bLd = (uint32_t)(((lane >> 4) & 1) * 8 + l7) * ROWB + ((lane >> 3) & 1) * 16;
    const uint32_t vLd = (uint32_t)(((lane >> 3) & 1) * 8 + l7) * ROWB + ((lane >> 4) & 1) * 16;

    for (int i = tid; i < 128 * 8; i += 256) {
        const int r = i >> 3, g = i & 7;
        *(uint4*)((char*)uQ + r * ROWB + g * 16) =
            *(const uint4*)(q + bh + (size_t)(qs + r) * CD + g * 8);
    }
    __syncthreads();

    uint32_t qf[4][4];
    #pragma unroll
    for (int kb = 0; kb < 4; kb++)
        ldsm4(qf[kb], sQ + (uint32_t)(warp * 16) * ROWB + aLd + kb * 32);

    float m[2] = {-1e30f, -1e30f}, l[2] = {0.f, 0.f};
    float o[8][4];
    #pragma unroll
    for (int j = 0; j < 8; j++)
        #pragma unroll
        for (int t = 0; t < 4; t++) o[j][t] = 0.f;

    const int qrow0 = qs + warp * 16;
    const int nk = 2 * qtb + 2;

    {
        const int r = tid >> 3, g = tid & 7;
        #pragma unroll
        for (int p = 0; p < 2; p++) {
            const int rr = r + p * 32;
            cp16(kvBase[0] + rr * ROWB + g * 16, k + bh + (size_t)rr * CD + g * 8);
            cp16(kvBase[0] + KV_H * 2 + rr * ROWB + g * 16, v + bh + (size_t)rr * CD + g * 8);
        }
        CP_COMMIT();
    }

    for (int kt = 0; kt < nk; kt++) {
        CP_WAIT0();
        __syncthreads();
        if (kt + 1 < nk) {
            const uint32_t dstb = kvBase[(kt + 1) & 1];
            const int ks1 = (kt + 1) * 64;
            const int r = tid >> 3, g = tid & 7;
            #pragma unroll
            for (int p = 0; p < 2; p++) {
                const int rr = r + p * 32;
                cp16(dstb + rr * ROWB + g * 16, k + bh + (size_t)(ks1 + rr) * CD + g * 8);
                cp16(dstb + KV_H * 2 + rr * ROWB + g * 16, v + bh + (size_t)(ks1 + rr) * CD + g * 8);
            }
        }
        CP_COMMIT();

        const int ks = kt * 64;
        const uint32_t sK = kvBase[kt & 1];
        const uint32_t sV = sK + KV_H * 2;

        float sf[8][4];
        #pragma unroll
        for (int j = 0; j < 8; j++)
            #pragma unroll
            for (int t = 0; t < 4; t++) sf[j][t] = 0.f;
        #pragma unroll
        for (int kb = 0; kb < 4; kb++) {
            uint32_t bf[4][4];
            #pragma unroll
            for (int p = 0; p < 4; p++)
                ldsm4(bf[p], sK + (uint32_t)(p * 16) * ROWB + bLd + kb * 32);
            #pragma unroll
            for (int j = 0; j < 8; j++)
                mma_f16(sf[j], qf[kb], &bf[j >> 1][(j & 1) * 2]);
        }

        if (ks + 63 > qrow0) {
            const int qr0 = qrow0 + gid, qr1 = qr0 + 8;
            #pragma unroll
            for (int j = 0; j < 8; j++) {
                const int kc = ks + j * 8 + 2 * tig;
                if (kc > qr0)     sf[j][0] = -1e30f;
                if (kc + 1 > qr0) sf[j][1] = -1e30f;
                if (kc > qr1)     sf[j][2] = -1e30f;
                if (kc + 1 > qr1) sf[j][3] = -1e30f;
            }
        }

        #pragma unroll
        for (int r = 0; r < 2; r++) {
            float mx = -1e30f;
            #pragma unroll
            for (int j = 0; j < 8; j++)
                mx = fmaxf(mx, fmaxf(sf[j][2 * r], sf[j][2 * r + 1]));
            mx = fmaxf(mx, __shfl_xor_sync(0xffffffffu, mx, 1));
            mx = fmaxf(mx, __shfl_xor_sync(0xffffffffu, mx, 2));
            const float mnew = fmaxf(m[r], mx);
            const float alpha = exp2f(m[r] - mnew);
            float rs = 0.f;
            #pragma unroll
            for (int j = 0; j < 8; j++) {
                float p0 = exp2f(sf[j][2 * r] - mnew);
                float p1 = exp2f(sf[j][2 * r + 1] - mnew);
                sf[j][2 * r] = p0; sf[j][2 * r + 1] = p1;
                rs += p0 + p1;
            }
            rs += __shfl_xor_sync(0xffffffffu, rs, 1);
            rs += __shfl_xor_sync(0xffffffffu, rs, 2);
            l[r] = l[r] * alpha + rs;
            m[r] = mnew;
            #pragma unroll
            for (int j = 0; j < 8; j++) { o[j][2 * r] *= alpha; o[j][2 * r + 1] *= alpha; }
        }

        #pragma unroll
        for (int kb = 0; kb < 4; kb++) {
            uint32_t pa[4];
            pa[0] = packh2(sf[2 * kb][0],     sf[2 * kb][1]);
            pa[1] = packh2(sf[2 * kb][2],     sf[2 * kb][3]);
            pa[2] = packh2(sf[2 * kb + 1][0], sf[2 * kb + 1][1]);
            pa[3] = packh2(sf[2 * kb + 1][2], sf[2 * kb + 1][3]);
            uint32_t vf[4][4];
            #pragma unroll
            for (int p = 0; p < 4; p++)
                ldsm4t(vf[p], sV + (uint32_t)(kb * 16) * ROWB + vLd + p * 32);
            #pragma unroll
            for (int j = 0; j < 8; j++)
                mma_f16(o[j], pa, &vf[j >> 1][(j & 1) * 2]);
        }
    }

    const float inv0 = 1.f / l[0], inv1 = 1.f / l[1];
    const int qa0 = qs + warp * 16 + gid, qa1 = qa0 + 8;
    #pragma unroll
    for (int j = 0; j < 8; j++) {
        const int cc = j * 8 + 2 * tig;
        *(uint32_t*)(y + bh + (size_t)qa0 * CD + cc) = packh2(o[j][0] * inv0, o[j][1] * inv0);
        *(uint32_t*)(y + bh + (size_t)qa1 * CD + cc) = packh2(o[j][2] * inv1, o[j][3] * inv1);
    }
}

// ---------------- launch ----------------
extern "C" void kernel_launch(void* const* d_in, const int* in_sizes, int n_in,
                              void* d_out, int out_size) {
    const float* x   = (const float*)d_in[0];
    const float* cs  = (const float*)d_in[1];
    const float* sn  = (const float*)d_in[2];
    const float* wq  = (const float*)d_in[3];
    const float* wk  = (const float*)d_in[4];
    const float* wv  = (const float*)d_in[5];
    const float* wo  = (const float*)d_in[6];
    const float* wfc = (const float*)d_in[7];
    const float* wpr = (const float*)d_in[8];
    const float* g1  = (const float*)d_in[9];
    const float* g2  = (const float*)d_in[10];
    float* out = (float*)d_out;

    __half *h, *q, *k, *v, *y, *ff;
    __half *wqt, *wkt, *wvt, *wot, *wfct, *wprt;
    float *x2;
    cudaGetSymbolAddress((void**)&h,  g_h);
    cudaGetSymbolAddress((void**)&q,  g_q);
    cudaGetSymbolAddress((void**)&k,  g_k);
    cudaGetSymbolAddress((void**)&v,  g_v);
    cudaGetSymbolAddress((void**)&y,  g_y);
    cudaGetSymbolAddress((void**)&ff, g_ff);
    cudaGetSymbolAddress((void**)&x2, g_x2);
    cudaGetSymbolAddress((void**)&wqt,  g_wqt);
    cudaGetSymbolAddress((void**)&wkt,  g_wkt);
    cudaGetSymbolAddress((void**)&wvt,  g_wvt);
    cudaGetSymbolAddress((void**)&wot,  g_wot);
    cudaGetSymbolAddress((void**)&wfct, g_wfct);
    cudaGetSymbolAddress((void**)&wprt, g_wprt);

    cudaFuncSetAttribute((const void*)attn_f16,
                         cudaFuncAttributeMaxDynamicSharedMemorySize, ATTN_SMEM);
    cudaFuncSetAttribute((const void*)qkv_gemm,
                         cudaFuncAttributeMaxDynamicSharedMemorySize, GEMM_SMEM);
    cudaFuncSetAttribute((const void*)gemm64_f16<1>,
                         cudaFuncAttributeMaxDynamicSharedMemorySize, GEMM64_SMEM);
    cudaFuncSetAttribute((const void*)gemm64_f16<2>,
                         cudaFuncAttributeMaxDynamicSharedMemorySize, GEMM64_SMEM);

    // 0. batched transpose+convert
    transp_all<<<dim3(96, 24, 6), 256>>>(wq, wk, wv, wo, wfc, wpr,
                                         wqt, wkt, wvt, wot, wfct, wprt);

    // 1. h = rmsnorm(x, g1)
    rmsnorm_kernel<<<NROWS, 256>>>(x, g1, h);

    // 2+3. q,k,v with RoPE fused, q pre-scaled
    qkv_gemm<<<dim3(18, 32), 256, GEMM_SMEM>>>(h, wqt, wkt, wvt, cs, sn, q, k, v);

    // 4. attention -> y
    attn_f16<<<dim3(TT / 128, HH, BB), 256, ATTN_SMEM>>>(q, k, v, y);

    // 5. x2 = x + y @ wo   (BN=64: 12x32 = 384 CTAs)
    gemm64_f16<1><<<dim3(CD / 64, NROWS / 128), 256, GEMM64_SMEM>>>(y, wot, x, x2, CD, CD);

    // 6. h = rmsnorm(x2, g2)
    rmsnorm_kernel<<<NROWS, 256>>>(x2, g2, h);

    // 7. ff = relu(h @ wfc)^2  (BN=64: 48x32 = 1536 CTAs)
    gemm64_f16<2><<<dim3(FFD / 64, NROWS / 128), 256, GEMM64_SMEM>>>(h, wfct, nullptr, ff, FFD, CD);

    // 8. out = x2 + ff @ wpr  (BN=64)
    gemm64_f16<1><<<dim3(CD / 64, NROWS / 128), 256, GEMM64_SMEM>>>(ff, wprt, x2, out, CD, FFD);
}

// round 12
// speedup vs baseline: 2.2052x; 1.1215x over previous
#include <cuda_runtime.h>
#include <cuda_fp16.h>
#include <math.h>
#include <stdint.h>

// Problem constants
#define BB 2
#define TT 2048
#define CD 768
#define HH 12
#define HDIM 64
#define DD2 32
#define FFD 3072
#define NROWS (BB*TT)          // 4096
static __device__ __constant__ float kEPS = 1e-5f;
#define LOG2E 1.44269504088896340736f

// ---------------- scratch ----------------
__device__ __half g_h [NROWS*CD];
__device__ __half g_q [NROWS*CD];
__device__ __half g_k [NROWS*CD];
__device__ __half g_v [NROWS*CD];
__device__ __half g_y [NROWS*CD];
__device__ __half g_ff[NROWS*FFD];
__device__ float  g_x2[NROWS*CD];
__device__ __half g_wqt [CD*CD];
__device__ __half g_wkt [CD*CD];
__device__ __half g_wvt [CD*CD];
__device__ __half g_wot [CD*CD];
__device__ __half g_wfct[FFD*CD];
__device__ __half g_wprt[CD*FFD];

// ---------------- helpers ----------------
__device__ __forceinline__ void mma_f16(float* c, const uint32_t* a, const uint32_t* b) {
    asm volatile(
        "mma.sync.aligned.m16n8k16.row.col.f32.f16.f16.f32 "
        "{%0,%1,%2,%3}, {%4,%5,%6,%7}, {%8,%9}, {%0,%1,%2,%3};"
        : "+f"(c[0]), "+f"(c[1]), "+f"(c[2]), "+f"(c[3])
        : "r"(a[0]), "r"(a[1]), "r"(a[2]), "r"(a[3]), "r"(b[0]), "r"(b[1]));
}
__device__ __forceinline__ void ldsm4(uint32_t* r, uint32_t addr) {
    asm volatile("ldmatrix.sync.aligned.m8n8.x4.shared.b16 {%0,%1,%2,%3}, [%4];"
                 : "=r"(r[0]), "=r"(r[1]), "=r"(r[2]), "=r"(r[3]) : "r"(addr));
}
__device__ __forceinline__ void ldsm4t(uint32_t* r, uint32_t addr) {
    asm volatile("ldmatrix.sync.aligned.m8n8.x4.trans.shared.b16 {%0,%1,%2,%3}, [%4];"
                 : "=r"(r[0]), "=r"(r[1]), "=r"(r[2]), "=r"(r[3]) : "r"(addr));
}
__device__ __forceinline__ uint32_t smem_u32(const void* p) {
    uint32_t a;
    asm("{ .reg .u64 t; cvta.to.shared.u64 t, %1; cvt.u32.u64 %0, t; }" : "=r"(a) : "l"(p));
    return a;
}
__device__ __forceinline__ void cp16(uint32_t dst, const void* src) {
    asm volatile("cp.async.cg.shared.global [%0], [%1], 16;" :: "r"(dst), "l"(src));
}
#define CP_COMMIT() asm volatile("cp.async.commit_group;" ::: "memory")
#define CP_WAIT1()  asm volatile("cp.async.wait_group 1;" ::: "memory")
#define CP_WAIT0()  asm volatile("cp.async.wait_group 0;" ::: "memory")
__device__ __forceinline__ uint32_t packh2(float a, float b) {
    __half2 h = __floats2half2_rn(a, b);
    return *(uint32_t*)&h;
}

// ---------------- batched weight transpose+convert ----------------
__global__ __launch_bounds__(256) void transp_all(
    const float* __restrict__ wq, const float* __restrict__ wk,
    const float* __restrict__ wv, const float* __restrict__ wo,
    const float* __restrict__ wfc, const float* __restrict__ wpr,
    __half* __restrict__ wqt, __half* __restrict__ wkt,
    __half* __restrict__ wvt, __half* __restrict__ wot,
    __half* __restrict__ wfct, __half* __restrict__ wprt) {
    const int z = blockIdx.z, a = blockIdx.x, b = blockIdx.y;
    const float* src; __half* dst; int R, C, c0, r0;
    if (z < 4) {
        if (a >= 24) return;
        src = (z == 0) ? wq : (z == 1) ? wk : (z == 2) ? wv : wo;
        dst = (z == 0) ? wqt : (z == 1) ? wkt : (z == 2) ? wvt : wot;
        R = CD; C = CD; c0 = a * 32; r0 = b * 32;
    } else if (z == 4) {
        src = wfc; dst = wfct; R = CD; C = FFD; c0 = a * 32; r0 = b * 32;
    } else {
        src = wpr; dst = wprt; R = FFD; C = CD; c0 = b * 32; r0 = a * 32;
    }
    __shared__ float t[32][33];
    const int tx = threadIdx.x & 31, ty = threadIdx.x >> 5;
    #pragma unroll
    for (int p = 0; p < 4; p++)
        t[ty + p * 8][tx] = src[(size_t)(r0 + ty + p * 8) * C + c0 + tx];
    __syncthreads();
    #pragma unroll
    for (int p = 0; p < 4; p++)
        dst[(size_t)(c0 + ty + p * 8) * R + r0 + tx] = __float2half_rn(t[tx][ty + p * 8]);
}

// SMEM geometry (padded, BN=128 path + attention)
#define STH 72
#define STW 36
#define ROWB 144
#define A_ST_B (128 * ROWB)             // 18432
#define STAGE_B (2 * A_ST_B)            // 36864
#define NSTAGE 3
#define GEMM_SMEM (NSTAGE * STAGE_B)    // 110592
// swizzled BN=64 path: exact 128B rows
#define A64_B (128 * 128)               // 16384
#define B64_B (64 * 128)                // 8192
#define STAGE64_B (A64_B + B64_B)       // 24576
#define GEMM64_SMEM (NSTAGE * STAGE64_B) // 73728

// ============ fp16 GEMM core BN=128 (padded rows): 256 thr, warp 32x64 ============
struct GemmAcc { float c[2][8][4]; };

__device__ __forceinline__ void gemm_mainloop(const __half* __restrict__ A,
                                              const __half* __restrict__ Wt,
                                              int K, int bm, int bn, char* sm,
                                              GemmAcc& G) {
    const int tid = threadIdx.x;
    const int warp = tid >> 5, lane = tid & 31;
    const int wy = warp >> 1, wx = warp & 1;

    #pragma unroll
    for (int i = 0; i < 2; i++)
        #pragma unroll
        for (int j = 0; j < 8; j++)
            #pragma unroll
            for (int t = 0; t < 4; t++) G.c[i][j][t] = 0.f;

    const int NC = K >> 6;
    const uint32_t sbase = smem_u32(sm);

    const int row = tid >> 1, gb = (tid & 1) * 4;
    const __half* Ab = A + (size_t)(bm + row) * K + gb * 8;
    const __half* Bb = Wt + (size_t)(bn + row) * K + gb * 8;
    const uint32_t aOff = (uint32_t)(row * ROWB + gb * 16);
    const uint32_t bOff = (uint32_t)(A_ST_B + row * ROWB + gb * 16);

    const int l7 = lane & 7;
    const uint32_t aLd = (uint32_t)(wy * 32 + ((lane >> 3) & 1) * 8 + l7) * ROWB + (lane >> 4) * 16;
    const uint32_t bLd = (uint32_t)(wx * 64 + ((lane >> 4) & 1) * 8 + l7) * ROWB + ((lane >> 3) & 1) * 16;

    #pragma unroll
    for (int s = 0; s < 2; s++) {
        const uint32_t st = sbase + s * STAGE_B;
        #pragma unroll
        for (int p = 0; p < 4; p++) cp16(st + aOff + p * 16, Ab + s * 64 + p * 8);
        #pragma unroll
        for (int p = 0; p < 4; p++) cp16(st + bOff + p * 16, Bb + s * 64 + p * 8);
        CP_COMMIT();
    }

    int s = 0;
    for (int c = 0; c < NC; c++) {
        CP_WAIT1();
        __syncthreads();
        if (c + 2 < NC) {
            const int s2 = (s + 2 >= NSTAGE) ? s + 2 - NSTAGE : s + 2;
            const uint32_t st = sbase + s2 * STAGE_B;
            #pragma unroll
            for (int p = 0; p < 4; p++) cp16(st + aOff + p * 16, Ab + (c + 2) * 64 + p * 8);
            #pragma unroll
            for (int p = 0; p < 4; p++) cp16(st + bOff + p * 16, Bb + (c + 2) * 64 + p * 8);
        }
        CP_COMMIT();

        const uint32_t aBase = sbase + s * STAGE_B + aLd;
        const uint32_t bBase = sbase + s * STAGE_B + A_ST_B + bLd;
        #pragma unroll
        for (int ks = 0; ks < 4; ks++) {
            uint32_t af[2][4], bf[4][4];
            ldsm4(af[0], aBase + ks * 32);
            ldsm4(af[1], aBase + 16 * ROWB + ks * 32);
            #pragma unroll
            for (int p = 0; p < 4; p++) ldsm4(bf[p], bBase + p * 16 * ROWB + ks * 32);
            #pragma unroll
            for (int i = 0; i < 2; i++)
                #pragma unroll
                for (int j = 0; j < 8; j++)
                    mma_f16(G.c[i][j], af[i], &bf[j >> 1][(j & 1) * 2]);
        }
        s = (s + 1 >= NSTAGE) ? 0 : s + 1;
    }
}

// ============ fp16 GEMM core BN=64, XOR-swizzled 128B rows, 3 CTAs/SM ============
// smem: A 128x128B, B 64x128B per stage. granule column ^= (row & 7).
__device__ __forceinline__ void gemm_mainloop64(const __half* __restrict__ A,
                                                const __half* __restrict__ Wt,
                                                int K, int bm, int bn, char* sm,
                                                float c64[2][4][4]) {
    const int tid = threadIdx.x;
    const int warp = tid >> 5, lane = tid & 31;
    const int wy = warp >> 1, wx = warp & 1;

    #pragma unroll
    for (int i = 0; i < 2; i++)
        #pragma unroll
        for (int j = 0; j < 4; j++)
            #pragma unroll
            for (int t = 0; t < 4; t++) c64[i][j][t] = 0.f;

    const int NC = K >> 6;
    const uint32_t sbase = smem_u32(sm);

    // A staging: row = tid>>1, granules (tid&1)*4 .. +3
    const int rowA = tid >> 1, gA = (tid & 1) * 4;
    const __half* Ab = A + (size_t)(bm + rowA) * K + gA * 8;
    const uint32_t aRow = (uint32_t)rowA * 128;
    const int aMsk = rowA & 7;
    // B staging: row = tid>>2, granules (tid&3)*2 .. +1
    const int rowB = tid >> 2, gB = (tid & 3) * 2;
    const __half* Bb = Wt + (size_t)(bn + rowB) * K + gB * 8;
    const uint32_t bRow = (uint32_t)(A64_B + rowB * 128);
    const int bMsk = rowB & 7;

    // ldsm lane maps
    const int l7 = lane & 7;
    const int rA = wy * 32 + ((lane >> 3) & 1) * 8 + l7;   // +i*16
    const int cA = lane >> 4;                               // granule 0/1
    const int mA = rA & 7;
    const int rB = wx * 32 + ((lane >> 4) & 1) * 8 + l7;   // +p*16
    const int cB = (lane >> 3) & 1;
    const int mB = rB & 7;

    #pragma unroll
    for (int s = 0; s < 2; s++) {
        const uint32_t st = sbase + s * STAGE64_B;
        #pragma unroll
        for (int p = 0; p < 4; p++)
            cp16(st + aRow + (((gA + p) ^ aMsk) * 16), Ab + s * 64 + p * 8);
        #pragma unroll
        for (int p = 0; p < 2; p++)
            cp16(st + bRow + (((gB + p) ^ bMsk) * 16), Bb + s * 64 + p * 8);
        CP_COMMIT();
    }

    int s = 0;
    for (int c = 0; c < NC; c++) {
        CP_WAIT1();
        __syncthreads();
        if (c + 2 < NC) {
            const int s2 = (s + 2 >= NSTAGE) ? s + 2 - NSTAGE : s + 2;
            const uint32_t st = sbase + s2 * STAGE64_B;
            #pragma unroll
            for (int p = 0; p < 4; p++)
                cp16(st + aRow + (((gA + p) ^ aMsk) * 16), Ab + (c + 2) * 64 + p * 8);
            #pragma unroll
            for (int p = 0; p < 2; p++)
                cp16(st + bRow + (((gB + p) ^ bMsk) * 16), Bb + (c + 2) * 64 + p * 8);
        }
        CP_COMMIT();

        const uint32_t stA = sbase + s * STAGE64_B;
        const uint32_t stB = stA + A64_B;
        #pragma unroll
        for (int ks = 0; ks < 4; ks++) {
            uint32_t af[2][4], bf[2][4];
            const uint32_t ca = (uint32_t)(((cA + 2 * ks) ^ mA) * 16);
            ldsm4(af[0], stA + (uint32_t)rA * 128 + ca);
            ldsm4(af[1], stA + (uint32_t)(rA + 16) * 128 + ca);
            const uint32_t cb = (uint32_t)(((cB + 2 * ks) ^ mB) * 16);
            ldsm4(bf[0], stB + (uint32_t)rB * 128 + cb);
            ldsm4(bf[1], stB + (uint32_t)(rB + 16) * 128 + cb);
            #pragma unroll
            for (int i = 0; i < 2; i++)
                #pragma unroll
                for (int j = 0; j < 4; j++)
                    mma_f16(c64[i][j], af[i], &bf[j >> 1][(j & 1) * 2]);
        }
        s = (s + 1 >= NSTAGE) ? 0 : s + 1;
    }
}

// ============ GEMM kernels ============
template <int EPI>
__global__ __launch_bounds__(256, 3) void gemm64_f16(const __half* __restrict__ A,
                                                     const __half* __restrict__ Wt,
                                                     const float* __restrict__ R,
                                                     void* __restrict__ OutV,
                                                     int N, int K) {
    extern __shared__ char sm[];
    const int bm = blockIdx.y * 128, bn = blockIdx.x * 64;
    float c64[2][4][4];
    gemm_mainloop64(A, Wt, K, bm, bn, sm, c64);

    const int tid = threadIdx.x;
    const int warp = tid >> 5, lane = tid & 31;
    const int wy = warp >> 1, wx = warp & 1;
    const int gid = lane >> 2, tig = lane & 3;

    #pragma unroll
    for (int i = 0; i < 2; i++) {
        const int r0 = bm + wy * 32 + i * 16 + gid;
        const int r1 = r0 + 8;
        #pragma unroll
        for (int j = 0; j < 4; j++) {
            const int cc = bn + wx * 32 + j * 8 + 2 * tig;
            float v0 = c64[i][j][0], v1 = c64[i][j][1];
            float v2 = c64[i][j][2], v3 = c64[i][j][3];
            if (EPI == 1) {
                float* Out = (float*)OutV;
                float2 t0 = *(const float2*)(R + (size_t)r0 * N + cc);
                float2 t1 = *(const float2*)(R + (size_t)r1 * N + cc);
                *(float2*)(Out + (size_t)r0 * N + cc) = make_float2(v0 + t0.x, v1 + t0.y);
                *(float2*)(Out + (size_t)r1 * N + cc) = make_float2(v2 + t1.x, v3 + t1.y);
            } else {
                __half* Out = (__half*)OutV;
                v0 = fmaxf(v0, 0.f); v1 = fmaxf(v1, 0.f);
                v2 = fmaxf(v2, 0.f); v3 = fmaxf(v3, 0.f);
                *(uint32_t*)(Out + (size_t)r0 * N + cc) = packh2(v0 * v0, v1 * v1);
                *(uint32_t*)(Out + (size_t)r1 * N + cc) = packh2(v2 * v2, v3 * v3);
            }
        }
    }
}

// ============ fused QKV GEMM + RoPE (q pre-scaled by 0.125*log2e) ============
__global__ __launch_bounds__(256, 2) void qkv_gemm(const __half* __restrict__ A,
                                                   const __half* __restrict__ wqt,
                                                   const __half* __restrict__ wkt,
                                                   const __half* __restrict__ wvt,
                                                   const float* __restrict__ cs,
                                                   const float* __restrict__ sn,
                                                   __half* __restrict__ q,
                                                   __half* __restrict__ k,
                                                   __half* __restrict__ v) {
    extern __shared__ char sm[];
    const int mat = blockIdx.x / 6;
    const int bn = (blockIdx.x % 6) * 128;
    const int bm = blockIdx.y * 128;
    const __half* Wt = (mat == 0) ? wqt : (mat == 1) ? wkt : wvt;
    __half* Out = (mat == 0) ? q : (mat == 1) ? k : v;
    const float sc = (mat == 0) ? 0.125f * LOG2E : 1.0f;

    GemmAcc G;
    gemm_mainloop(A, Wt, CD, bm, bn, sm, G);

    const int tid = threadIdx.x;
    const int warp = tid >> 5, lane = tid & 31;
    const int wy = warp >> 1, wx = warp & 1;
    const int gid = lane >> 2, tig = lane & 3;

    if (mat == 2) {
        #pragma unroll
        for (int i = 0; i < 2; i++) {
            const int r0 = bm + wy * 32 + i * 16 + gid;
            const int r1 = r0 + 8;
            #pragma unroll
            for (int j = 0; j < 8; j++) {
                const int cc = bn + wx * 64 + j * 8 + 2 * tig;
                *(uint32_t*)(Out + (size_t)r0 * CD + cc) = packh2(G.c[i][j][0], G.c[i][j][1]);
                *(uint32_t*)(Out + (size_t)r1 * CD + cc) = packh2(G.c[i][j][2], G.c[i][j][3]);
            }
        }
    } else {
        #pragma unroll
        for (int i = 0; i < 2; i++) {
            const int r0 = bm + wy * 32 + i * 16 + gid;
            const int r1 = r0 + 8;
            const int t0 = r0 & (TT - 1), t1 = r1 & (TT - 1);
            #pragma unroll
            for (int j = 0; j < 4; j++) {
                const int d = j * 8 + 2 * tig;
                const int cc = bn + wx * 64 + j * 8 + 2 * tig;
                float2 c0 = *(const float2*)(cs + t0 * DD2 + d);
                float2 s0 = *(const float2*)(sn + t0 * DD2 + d);
                float2 c1 = *(const float2*)(cs + t1 * DD2 + d);
                float2 s1 = *(const float2*)(sn + t1 * DD2 + d);
                float x1a = G.c[i][j][0], x1b = G.c[i][j][1];
                float x2a = G.c[i][j + 4][0], x2b = G.c[i][j + 4][1];
                *(uint32_t*)(Out + (size_t)r0 * CD + cc) =
                    packh2(sc * (x1a * c0.x + x2a * s0.x), sc * (x1b * c0.y + x2b * s0.y));
                *(uint32_t*)(Out + (size_t)r0 * CD + cc + 32) =
                    packh2(sc * (-x1a * s0.x + x2a * c0.x), sc * (-x1b * s0.y + x2b * c0.y));
                float y1a = G.c[i][j][2], y1b = G.c[i][j][3];
                float y2a = G.c[i][j + 4][2], y2b = G.c[i][j + 4][3];
                *(uint32_t*)(Out + (size_t)r1 * CD + cc) =
                    packh2(sc * (y1a * c1.x + y2a * s1.x), sc * (y1b * c1.y + y2b * s1.y));
                *(uint32_t*)(Out + (size_t)r1 * CD + cc + 32) =
                    packh2(sc * (-y1a * s1.x + y2a * c1.x), sc * (-y1b * s1.y + y2b * c1.y));
            }
        }
    }
}

// ---------------- RMSNorm: f32 in, half out ----------------
__global__ __launch_bounds__(256) void rmsnorm_kernel(const float* __restrict__ x,
                                                      const float* __restrict__ g,
                                                      __half* __restrict__ out) {
    int row = blockIdx.x;
    const float* xr = x + (size_t)row * CD;
    float ss = 0.f;
    for (int i = threadIdx.x; i < CD; i += 256) { float v = xr[i]; ss += v * v; }
    #pragma unroll
    for (int o = 16; o; o >>= 1) ss += __shfl_xor_sync(0xffffffffu, ss, o);
    __shared__ float red[8];
    if ((threadIdx.x & 31) == 0) red[threadIdx.x >> 5] = ss;
    __syncthreads();
    float tot = 0.f;
    #pragma unroll
    for (int i = 0; i < 8; i++) tot += red[i];
    float rinv = rsqrtf(tot / (float)CD + kEPS);
    __half* orow = out + (size_t)row * CD;
    for (int i = threadIdx.x; i < CD; i += 256) orow[i] = __float2half_rn(g[i] * xr[i] * rinv);
}

// ---------------- fp16 Flash Attention (unchanged) ----------------
#define KV_H (64 * STH)
#define ATTN_SMEM ((128 * STH + 4 * KV_H) * 2)   // 55296 B
__global__ __launch_bounds__(256, 2) void attn_f16(const __half* __restrict__ q,
                                                   const __half* __restrict__ k,
                                                   const __half* __restrict__ v,
                                                   __half* __restrict__ y) {
    extern __shared__ char asmc[];
    __half* uQ = (__half*)asmc;

    const int h = blockIdx.y, b = blockIdx.z;
    const int qtb = (int)gridDim.x - 1 - (int)blockIdx.x;
    const int tid = threadIdx.x, warp = tid >> 5, lane = tid & 31;
    const int gid = lane >> 2, tig = lane & 3;
    const int qs = qtb * 128;
    const size_t bh = (size_t)b * TT * CD + (size_t)h * HDIM;

    const uint32_t sQ = smem_u32(uQ);
    const uint32_t kvBase[2] = { sQ + 128 * ROWB, sQ + 128 * ROWB + 2 * KV_H * 2 };
    const int l7 = lane & 7;
    const uint32_t aLd = (uint32_t)(((lane >> 3) & 1) * 8 + l7) * ROWB + (lane >> 4) * 16;
    const uint32_t bLd = (uint32_t)(((lane >> 4) & 1) * 8 + l7) * ROWB + ((lane >> 3) & 1) * 16;
    const uint32_t vLd = (uint32_t)(((lane >> 3) & 1) * 8 + l7) * ROWB + ((lane >> 4) & 1) * 16;

    for (int i = tid; i < 128 * 8; i += 256) {
        const int r = i >> 3, g = i & 7;
        *(uint4*)((char*)uQ + r * ROWB + g * 16) =
            *(const uint4*)(q + bh + (size_t)(qs + r) * CD + g * 8);
    }
    __syncthreads();

    uint32_t qf[4][4];
    #pragma unroll
    for (int kb = 0; kb < 4; kb++)
        ldsm4(qf[kb], sQ + (uint32_t)(warp * 16) * ROWB + aLd + kb * 32);

    float m[2] = {-1e30f, -1e30f}, l[2] = {0.f, 0.f};
    float o[8][4];
    #pragma unroll
    for (int j = 0; j < 8; j++)
        #pragma unroll
        for (int t = 0; t < 4; t++) o[j][t] = 0.f;

    const int qrow0 = qs + warp * 16;
    const int nk = 2 * qtb + 2;

    {
        const int r = tid >> 3, g = tid & 7;
        #pragma unroll
        for (int p = 0; p < 2; p++) {
            const int rr = r + p * 32;
            cp16(kvBase[0] + rr * ROWB + g * 16, k + bh + (size_t)rr * CD + g * 8);
            cp16(kvBase[0] + KV_H * 2 + rr * ROWB + g * 16, v + bh + (size_t)rr * CD + g * 8);
        }
        CP_COMMIT();
    }

    for (int kt = 0; kt < nk; kt++) {
        CP_WAIT0();
        __syncthreads();
        if (kt + 1 < nk) {
            const uint32_t dstb = kvBase[(kt + 1) & 1];
            const int ks1 = (kt + 1) * 64;
            const int r = tid >> 3, g = tid & 7;
            #pragma unroll
            for (int p = 0; p < 2; p++) {
                const int rr = r + p * 32;
                cp16(dstb + rr * ROWB + g * 16, k + bh + (size_t)(ks1 + rr) * CD + g * 8);
                cp16(dstb + KV_H * 2 + rr * ROWB + g * 16, v + bh + (size_t)(ks1 + rr) * CD + g * 8);
            }
        }
        CP_COMMIT();

        const int ks = kt * 64;
        const uint32_t sK = kvBase[kt & 1];
        const uint32_t sV = sK + KV_H * 2;

        float sf[8][4];
        #pragma unroll
        for (int j = 0; j < 8; j++)
            #pragma unroll
            for (int t = 0; t < 4; t++) sf[j][t] = 0.f;
        #pragma unroll
        for (int kb = 0; kb < 4; kb++) {
            uint32_t bf[4][4];
            #pragma unroll
            for (int p = 0; p < 4; p++)
                ldsm4(bf[p], sK + (uint32_t)(p * 16) * ROWB + bLd + kb * 32);
            #pragma unroll
            for (int j = 0; j < 8; j++)
                mma_f16(sf[j], qf[kb], &bf[j >> 1][(j & 1) * 2]);
        }

        if (ks + 63 > qrow0) {
            const int qr0 = qrow0 + gid, qr1 = qr0 + 8;
            #pragma unroll
            for (int j = 0; j < 8; j++) {
                const int kc = ks + j * 8 + 2 * tig;
                if (kc > qr0)     sf[j][0] = -1e30f;
                if (kc + 1 > qr0) sf[j][1] = -1e30f;
                if (kc > qr1)     sf[j][2] = -1e30f;
                if (kc + 1 > qr1) sf[j][3] = -1e30f;
            }
        }

        #pragma unroll
        for (int r = 0; r < 2; r++) {
            float mx = -1e30f;
            #pragma unroll
            for (int j = 0; j < 8; j++)
                mx = fmaxf(mx, fmaxf(sf[j][2 * r], sf[j][2 * r + 1]));
            mx = fmaxf(mx, __shfl_xor_sync(0xffffffffu, mx, 1));
            mx = fmaxf(mx, __shfl_xor_sync(0xffffffffu, mx, 2));
            const float mnew = fmaxf(m[r], mx);
            const float alpha = exp2f(m[r] - mnew);
            float rs = 0.f;
            #pragma unroll
            for (int j = 0; j < 8; j++) {
                float p0 = exp2f(sf[j][2 * r] - mnew);
                float p1 = exp2f(sf[j][2 * r + 1] - mnew);
                sf[j][2 * r] = p0; sf[j][2 * r + 1] = p1;
                rs += p0 + p1;
            }
            rs += __shfl_xor_sync(0xffffffffu, rs, 1);
            rs += __shfl_xor_sync(0xffffffffu, rs, 2);
            l[r] = l[r] * alpha + rs;
            m[r] = mnew;
            #pragma unroll
            for (int j = 0; j < 8; j++) { o[j][2 * r] *= alpha; o[j][2 * r + 1] *= alpha; }
        }

        #pragma unroll
        for (int kb = 0; kb < 4; kb++) {
            uint32_t pa[4];
            pa[0] = packh2(sf[2 * kb][0],     sf[2 * kb][1]);
            pa[1] = packh2(sf[2 * kb][2],     sf[2 * kb][3]);
            pa[2] = packh2(sf[2 * kb + 1][0], sf[2 * kb + 1][1]);
            pa[3] = packh2(sf[2 * kb + 1][2], sf[2 * kb + 1][3]);
            uint32_t vf[4][4];
            #pragma unroll
            for (int p = 0; p < 4; p++)
                ldsm4t(vf[p], sV + (uint32_t)(kb * 16) * ROWB + vLd + p * 32);
            #pragma unroll
            for (int j = 0; j < 8; j++)
                mma_f16(o[j], pa, &vf[j >> 1][(j & 1) * 2]);
        }
    }

    const float inv0 = 1.f / l[0], inv1 = 1.f / l[1];
    const int qa0 = qs + warp * 16 + gid, qa1 = qa0 + 8;
    #pragma unroll
    for (int j = 0; j < 8; j++) {
        const int cc = j * 8 + 2 * tig;
        *(uint32_t*)(y + bh + (size_t)qa0 * CD + cc) = packh2(o[j][0] * inv0, o[j][1] * inv0);
        *(uint32_t*)(y + bh + (size_t)qa1 * CD + cc) = packh2(o[j][2] * inv1, o[j][3] * inv1);
    }
}

// ---------------- launch ----------------
extern "C" void kernel_launch(void* const* d_in, const int* in_sizes, int n_in,
                              void* d_out, int out_size) {
    const float* x   = (const float*)d_in[0];
    const float* cs  = (const float*)d_in[1];
    const float* sn  = (const float*)d_in[2];
    const float* wq  = (const float*)d_in[3];
    const float* wk  = (const float*)d_in[4];
    const float* wv  = (const float*)d_in[5];
    const float* wo  = (const float*)d_in[6];
    const float* wfc = (const float*)d_in[7];
    const float* wpr = (const float*)d_in[8];
    const float* g1  = (const float*)d_in[9];
    const float* g2  = (const float*)d_in[10];
    float* out = (float*)d_out;

    __half *h, *q, *k, *v, *y, *ff;
    __half *wqt, *wkt, *wvt, *wot, *wfct, *wprt;
    float *x2;
    cudaGetSymbolAddress((void**)&h,  g_h);
    cudaGetSymbolAddress((void**)&q,  g_q);
    cudaGetSymbolAddress((void**)&k,  g_k);
    cudaGetSymbolAddress((void**)&v,  g_v);
    cudaGetSymbolAddress((void**)&y,  g_y);
    cudaGetSymbolAddress((void**)&ff, g_ff);
    cudaGetSymbolAddress((void**)&x2, g_x2);
    cudaGetSymbolAddress((void**)&wqt,  g_wqt);
    cudaGetSymbolAddress((void**)&wkt,  g_wkt);
    cudaGetSymbolAddress((void**)&wvt,  g_wvt);
    cudaGetSymbolAddress((void**)&wot,  g_wot);
    cudaGetSymbolAddress((void**)&wfct, g_wfct);
    cudaGetSymbolAddress((void**)&wprt, g_wprt);

    cudaFuncSetAttribute((const void*)attn_f16,
                         cudaFuncAttributeMaxDynamicSharedMemorySize, ATTN_SMEM);
    cudaFuncSetAttribute((const void*)qkv_gemm,
                         cudaFuncAttributeMaxDynamicSharedMemorySize, GEMM_SMEM);
    cudaFuncSetAttribute((const void*)gemm64_f16<1>,
                         cudaFuncAttributeMaxDynamicSharedMemorySize, GEMM64_SMEM);
    cudaFuncSetAttribute((const void*)gemm64_f16<2>,
                         cudaFuncAttributeMaxDynamicSharedMemorySize, GEMM64_SMEM);

    // 0. batched transpose+convert
    transp_all<<<dim3(96, 24, 6), 256>>>(wq, wk, wv, wo, wfc, wpr,
                                         wqt, wkt, wvt, wot, wfct, wprt);

    // 1. h = rmsnorm(x, g1)
    rmsnorm_kernel<<<NROWS, 256>>>(x, g1, h);

    // 2+3. q,k,v with RoPE fused, q pre-scaled
    qkv_gemm<<<dim3(18, 32), 256, GEMM_SMEM>>>(h, wqt, wkt, wvt, cs, sn, q, k, v);

    // 4. attention -> y
    attn_f16<<<dim3(TT / 128, HH, BB), 256, ATTN_SMEM>>>(q, k, v, y);

    // 5. x2 = x + y @ wo   (BN=64 swizzled, 3 CTA/SM: 384 CTAs < 444 slots)
    gemm64_f16<1><<<dim3(CD / 64, NROWS / 128), 256, GEMM64_SMEM>>>(y, wot, x, x2, CD, CD);

    // 6. h = rmsnorm(x2, g2)
    rmsnorm_kernel<<<NROWS, 256>>>(x2, g2, h);

    // 7. ff = relu(h @ wfc)^2
    gemm64_f16<2><<<dim3(FFD / 64, NROWS / 128), 256, GEMM64_SMEM>>>(h, wfct, nullptr, ff, FFD, CD);

    // 8. out = x2 + ff @ wpr
    gemm64_f16<1><<<dim3(CD / 64, NROWS / 128), 256, GEMM64_SMEM>>>(ff, wprt, x2, out, CD, FFD);
}